// round 6
// baseline (speedup 1.0000x reference)
#include <cuda_runtime.h>
#include <cuda_bf16.h>
#include <cstdint>

// Problem shape (fixed)
#define BB 32
#define SS 4096
#define HH 512
#define AA 256

#define TM 128              // rows per CTA
#define KC 64               // K per chunk
#define NCH (HH / KC)       // 8 chunks

// ---------------- scratch (no allocs allowed) ----------------
__device__ float g_scores[BB * SS];
__device__ float g_decp[BB * AA];
__device__ float g_ctx_part[BB * 32 * HH];
// W_enc^T split to bf16 hi/lo, [n=256][k=512] row-major (k contiguous)
__device__ __nv_bfloat16 g_Bh[AA * HH];
__device__ __nv_bfloat16 g_Bl[AA * HH];

// ---------------- helpers ----------------
__device__ __forceinline__ uint32_t smem_u32(const void* p) {
    uint32_t a;
    asm("{ .reg .u64 t; cvta.to.shared.u64 t, %1; cvt.u32.u64 %0, t; }"
        : "=r"(a) : "l"(p));
    return a;
}

__device__ __forceinline__ float fast_tanh(float x) {
    x = fminf(15.0f, fmaxf(-15.0f, x));
    float t = __expf(2.0f * x);
    return __fdividef(t - 1.0f, t + 1.0f);
}

__device__ __forceinline__ void ldm_x4(uint32_t* r, uint32_t addr) {
    asm volatile("ldmatrix.sync.aligned.m8n8.x4.shared.b16 {%0,%1,%2,%3}, [%4];"
                 : "=r"(r[0]), "=r"(r[1]), "=r"(r[2]), "=r"(r[3]) : "r"(addr));
}

__device__ __forceinline__ void mma16816(float* d, const uint32_t* a, const uint32_t* b) {
    asm volatile(
        "mma.sync.aligned.m16n8k16.row.col.f32.bf16.bf16.f32 "
        "{%0,%1,%2,%3}, {%4,%5,%6,%7}, {%8,%9}, {%0,%1,%2,%3};"
        : "+f"(d[0]), "+f"(d[1]), "+f"(d[2]), "+f"(d[3])
        : "r"(a[0]), "r"(a[1]), "r"(a[2]), "r"(a[3]), "r"(b[0]), "r"(b[1]));
}

#define CP16(dst, src) \
    asm volatile("cp.async.ca.shared.global [%0], [%1], 16;" :: "r"(dst), "l"(src) : "memory")
#define CP_COMMIT() asm volatile("cp.async.commit_group;" ::: "memory")
#define CP_WAIT0()  asm volatile("cp.async.wait_group 0;"  ::: "memory")

// ---------------------------------------------------------------------------
// prep: W_enc[k][n] -> g_Bh/g_Bl[n][k] bf16 hi/lo. grid(HH), block(AA).
// ---------------------------------------------------------------------------
__global__ void prep_B_kernel(const float* __restrict__ Wenc) {
    int k = blockIdx.x, n = threadIdx.x;
    float v = Wenc[k * AA + n];
    __nv_bfloat16 hi = __float2bfloat16(v);
    __nv_bfloat16 lo = __float2bfloat16(v - __bfloat162float(hi));
    g_Bh[n * HH + k] = hi;
    g_Bl[n * HH + k] = lo;
}

// ---------------------------------------------------------------------------
// k0: dec_p[b][a] = decoder_hidden[b] . W_dec[:,a] + b_dec[a]
// ---------------------------------------------------------------------------
__global__ void dec_proj_kernel(const float* __restrict__ dh,
                                const float* __restrict__ Wdec,
                                const float* __restrict__ bdec) {
    __shared__ float sdh[HH];
    int b = blockIdx.x, t = threadIdx.x;
    for (int k = t; k < HH; k += 256) sdh[k] = dh[b * HH + k];
    __syncthreads();
    float acc = bdec[t];
    #pragma unroll 8
    for (int k = 0; k < HH; k++) acc = fmaf(sdh[k], Wdec[k * AA + t], acc);
    g_decp[b * AA + t] = acc;
}

// ---------------------------------------------------------------------------
// k1: scores via mma.sync split-bf16, DOUBLE-BUFFERED mainloop.
// grid(1024), block(512). CTA tile 128x256, warp grid 4(M)x4(N).
// smem rows padded to 144B. Buffers: A[2] (hi+lo), B[2] (hi+lo).
// ---------------------------------------------------------------------------
#define RSTRIDE 144
#define AHALF   (128u * RSTRIDE)            // 18432
#define ABUF    (2u * AHALF)                // 36864 (hi + lo)
#define BHALF   (256u * RSTRIDE)            // 36864
#define BBUF    (2u * BHALF)                // 73728
#define SM_A0   0u
#define SM_A1   ABUF                        // 36864
#define SM_B0   (2u * ABUF)                 // 73728
#define SM_B1   (SM_B0 + BBUF)              // 147456
#define SM_BIAS (SM_B1 + BBUF)              // 221184
#define SM_WE   (SM_BIAS + 1024u)
#define SM_RED  (SM_WE + 1024u)
#define SM_TOT  (SM_RED + 2048u)            // 225280 bytes

__global__ __launch_bounds__(512) void scores_mma_kernel(
    const float* __restrict__ enc,
    const float* __restrict__ benc,
    const float* __restrict__ We) {

    extern __shared__ char smem[];
    const uint32_t sb = smem_u32(smem);
    const int tid  = threadIdx.x;
    const int wid  = tid >> 5;
    const int lane = tid & 31;
    const int wm = (wid & 3) * 32;
    const int wn = (wid >> 2) * 64;
    const int row0 = blockIdx.x * TM;       // 128 | 4096 -> never crosses batch
    const int batch = row0 / SS;

    float* sbias = (float*)(smem + SM_BIAS);
    float* swe   = (float*)(smem + SM_WE);
    float* red   = (float*)(smem + SM_RED);
    if (tid < AA) {
        sbias[tid] = benc[tid] + g_decp[batch * AA + tid];
        swe[tid]   = We[tid];
    }

    float acc[2][8][4];
    #pragma unroll
    for (int mt = 0; mt < 2; mt++)
        #pragma unroll
        for (int nt = 0; nt < 8; nt++)
            #pragma unroll
            for (int q = 0; q < 4; q++) acc[mt][nt][q] = 0.0f;

    // ldmatrix lane addressing
    const int a_r = (lane & 7) + ((lane >> 3) & 1) * 8;
    const int a_k = (lane >> 4) * 8;
    const int b_n = (lane & 7) + (lane >> 4) * 8;
    const int b_k = ((lane >> 3) & 1) * 8;

    // per-thread load indices (A: 4 float4 per chunk; B: 4x2 cp.async per chunk)
    const int am  = tid >> 2;                   // A row (2 rows per 8 threads? no: 512/4)
    const int ak4 = (tid & 3) * 16;             // 4 float4 groups? -> see loop below

    // ---- load helpers (lambdas keep register pressure explicit) ----
    auto issue_B = [&](int c, uint32_t bbase) {
        const char* bh = (const char*)g_Bh;
        const char* bl = (const char*)g_Bl;
        #pragma unroll
        for (int i = 0; i < 4; i++) {
            int idx = tid + i * 512;            // 0..2047
            int n   = idx >> 3;
            int ch  = idx & 7;
            size_t src = (size_t)(n * HH + c * KC + ch * 8) * 2;
            uint32_t dst = n * RSTRIDE + ch * 16;
            CP16(bbase + dst, bh + src);
            CP16(bbase + BHALF + dst, bl + src);
        }
    };
    auto load_A = [&](int c, float4* v) {
        const float* Ab = enc + (size_t)row0 * HH + c * KC;
        #pragma unroll
        for (int i = 0; i < 4; i++) {
            int idx = tid + i * 512;            // 0..2047 float4s
            int m   = idx >> 4;
            int k4  = (idx & 15) * 4;
            v[i] = *(const float4*)(Ab + (size_t)m * HH + k4);
        }
    };
    auto store_A = [&](const float4* v, uint32_t abase) {
        #pragma unroll
        for (int i = 0; i < 4; i++) {
            int idx = tid + i * 512;
            int m   = idx >> 4;
            int k4  = (idx & 15) * 4;
            float4 w = v[i];
            __nv_bfloat162 h01 = __floats2bfloat162_rn(w.x, w.y);
            __nv_bfloat162 h23 = __floats2bfloat162_rn(w.z, w.w);
            __nv_bfloat162 l01 = __floats2bfloat162_rn(
                w.x - __bfloat162float(h01.x), w.y - __bfloat162float(h01.y));
            __nv_bfloat162 l23 = __floats2bfloat162_rn(
                w.z - __bfloat162float(h23.x), w.w - __bfloat162float(h23.y));
            uint32_t off = m * RSTRIDE + k4 * 2;
            *(uint2*)(smem + abase + off) = make_uint2(*(uint32_t*)&h01, *(uint32_t*)&h23);
            *(uint2*)(smem + abase + AHALF + off) = make_uint2(*(uint32_t*)&l01, *(uint32_t*)&l23);
        }
    };

    // ---- prologue: chunk 0 into buffer 0 ----
    float4 av[4];
    issue_B(0, sb + SM_B0);
    CP_COMMIT();
    load_A(0, av);
    store_A(av, SM_A0);
    CP_WAIT0();
    __syncthreads();

    for (int c = 0; c < NCH; c++) {
        const uint32_t curA = (c & 1) ? SM_A1 : SM_A0;
        const uint32_t curB = sb + ((c & 1) ? SM_B1 : SM_B0);
        const uint32_t nxtA = (c & 1) ? SM_A0 : SM_A1;
        const uint32_t nxtB = sb + ((c & 1) ? SM_B0 : SM_B1);

        if (c + 1 < NCH) {
            issue_B(c + 1, nxtB);
            CP_COMMIT();
            load_A(c + 1, av);      // LDGs in flight during compute below
        }

        // ---- compute chunk c: 4 ksteps of 16 ----
        #pragma unroll
        for (int ks = 0; ks < 4; ks++) {
            const int k0 = ks * 16;
            uint32_t ah[2][4], al[2][4];
            #pragma unroll
            for (int mt = 0; mt < 2; mt++) {
                uint32_t ra = (wm + mt * 16 + a_r) * RSTRIDE + (k0 + a_k) * 2;
                ldm_x4(ah[mt], sb + curA + ra);
                ldm_x4(al[mt], sb + curA + AHALF + ra);
            }
            #pragma unroll
            for (int ntp = 0; ntp < 4; ntp++) {
                uint32_t rb = (wn + ntp * 16 + b_n) * RSTRIDE + (k0 + b_k) * 2;
                uint32_t bh[4], bl[4];
                ldm_x4(bh, curB + rb);
                ldm_x4(bl, curB + BHALF + rb);
                #pragma unroll
                for (int mt = 0; mt < 2; mt++)
                    #pragma unroll
                    for (int h = 0; h < 2; h++) {
                        float* d = acc[mt][ntp * 2 + h];
                        mma16816(d, ah[mt], &bh[h * 2]);   // hi*hi
                        mma16816(d, ah[mt], &bl[h * 2]);   // hi*lo
                        mma16816(d, al[mt], &bh[h * 2]);   // lo*hi
                    }
            }
        }

        if (c + 1 < NCH) {
            store_A(av, nxtA);
            CP_WAIT0();
        }
        __syncthreads();
    }

    // ---- fused epilogue: tanh(+bias)*We, reduce over 256 cols ----
    const int wnidx = wid >> 2;
    #pragma unroll
    for (int mt = 0; mt < 2; mt++) {
        int r_lo = wm + mt * 16 + (lane >> 2);
        float s0 = 0.0f, s1 = 0.0f;
        #pragma unroll
        for (int nt = 0; nt < 8; nt++) {
            int col = wn + nt * 8 + (lane & 3) * 2;
            float w0 = swe[col], w1 = swe[col + 1];
            float bb0 = sbias[col], bb1 = sbias[col + 1];
            s0 = fmaf(fast_tanh(acc[mt][nt][0] + bb0), w0, s0);
            s0 = fmaf(fast_tanh(acc[mt][nt][1] + bb1), w1, s0);
            s1 = fmaf(fast_tanh(acc[mt][nt][2] + bb0), w0, s1);
            s1 = fmaf(fast_tanh(acc[mt][nt][3] + bb1), w1, s1);
        }
        s0 += __shfl_xor_sync(0xffffffffu, s0, 1);
        s0 += __shfl_xor_sync(0xffffffffu, s0, 2);
        s1 += __shfl_xor_sync(0xffffffffu, s1, 1);
        s1 += __shfl_xor_sync(0xffffffffu, s1, 2);
        if ((lane & 3) == 0) {
            red[r_lo * 4 + wnidx]       = s0;
            red[(r_lo + 8) * 4 + wnidx] = s1;
        }
    }
    __syncthreads();
    if (tid < TM) {
        const float* rp = red + tid * 4;
        g_scores[row0 + tid] = rp[0] + rp[1] + rp[2] + rp[3];  // b_e omitted
    }
}

// ---------------------------------------------------------------------------
// k2: softmax over S per batch. grid(B), block(1024). Writes attn to d_out.
// ---------------------------------------------------------------------------
__global__ __launch_bounds__(1024) void softmax_kernel(float* __restrict__ attn_out) {
    __shared__ float sv[SS];
    __shared__ float red[32];
    int b = blockIdx.x, t = threadIdx.x;
    int warp = t >> 5, lane = t & 31;

    float m = -1e30f;
    #pragma unroll
    for (int i = t; i < SS; i += 1024) {
        float v = g_scores[b * SS + i];
        sv[i] = v;
        m = fmaxf(m, v);
    }
    #pragma unroll
    for (int off = 16; off > 0; off >>= 1)
        m = fmaxf(m, __shfl_down_sync(0xffffffffu, m, off));
    if (lane == 0) red[warp] = m;
    __syncthreads();
    if (t == 0) {
        float mm = red[0];
        #pragma unroll
        for (int w = 1; w < 32; w++) mm = fmaxf(mm, red[w]);
        red[0] = mm;
    }
    __syncthreads();
    m = red[0];
    __syncthreads();

    float sum = 0.0f;
    #pragma unroll
    for (int i = t; i < SS; i += 1024) {
        float e = __expf(sv[i] - m);
        sv[i] = e;
        sum += e;
    }
    #pragma unroll
    for (int off = 16; off > 0; off >>= 1)
        sum += __shfl_down_sync(0xffffffffu, sum, off);
    if (lane == 0) red[warp] = sum;
    __syncthreads();
    if (t == 0) {
        float ss = 0.0f;
        #pragma unroll
        for (int w = 0; w < 32; w++) ss += red[w];
        red[0] = 1.0f / ss;
    }
    __syncthreads();
    float inv = red[0];
    #pragma unroll
    for (int i = t; i < SS; i += 1024)
        attn_out[b * SS + i] = sv[i] * inv;
}

// ---------------------------------------------------------------------------
// k3/k4: context, deterministic 2-stage
// ---------------------------------------------------------------------------
__global__ void context_partial_kernel(const float* __restrict__ enc,
                                       const float* __restrict__ attn) {
    __shared__ float sa[128];
    int b  = blockIdx.y;
    int s0 = blockIdx.x * 128;
    int h  = threadIdx.x;
    if (h < 128) sa[h] = attn[b * SS + s0 + h];
    __syncthreads();
    const float* base = enc + ((size_t)b * SS + s0) * HH + h;
    float acc = 0.0f;
    #pragma unroll 16
    for (int s = 0; s < 128; s++)
        acc = fmaf(sa[s], base[(size_t)s * HH], acc);
    g_ctx_part[(b * 32 + blockIdx.x) * HH + h] = acc;
}

__global__ void context_reduce_kernel(float* __restrict__ ctx_out) {
    int b = blockIdx.x, h = threadIdx.x;
    float acc = 0.0f;
    #pragma unroll
    for (int sc = 0; sc < 32; sc++)
        acc += g_ctx_part[(b * 32 + sc) * HH + h];
    ctx_out[b * HH + h] = acc;
}

// ---------------------------------------------------------------------------
// entry point
// ---------------------------------------------------------------------------
extern "C" void kernel_launch(void* const* d_in, const int* in_sizes, int n_in,
                              void* d_out, int out_size) {
    const float* enc  = (const float*)d_in[0];
    const float* dh   = (const float*)d_in[1];
    const float* Wenc = (const float*)d_in[2];
    const float* benc = (const float*)d_in[3];
    const float* Wdec = (const float*)d_in[4];
    const float* bdec = (const float*)d_in[5];
    const float* We   = (const float*)d_in[6];

    float* ctx_out  = (float*)d_out;             // [B, H]
    float* attn_out = (float*)d_out + BB * HH;   // [B, S]

    cudaFuncSetAttribute(scores_mma_kernel,
                         cudaFuncAttributeMaxDynamicSharedMemorySize, SM_TOT);

    prep_B_kernel<<<HH, AA>>>(Wenc);
    dec_proj_kernel<<<BB, 256>>>(dh, Wdec, bdec);
    scores_mma_kernel<<<(BB * SS) / TM, 512, SM_TOT>>>(enc, benc, We);
    softmax_kernel<<<BB, 1024>>>(attn_out);
    context_partial_kernel<<<dim3(32, BB), HH>>>(enc, attn_out);
    context_reduce_kernel<<<BB, HH>>>(ctx_out);
}

// round 7
// speedup vs baseline: 1.0554x; 1.0554x over previous
#include <cuda_runtime.h>
#include <cuda_bf16.h>
#include <cstdint>

// Problem shape (fixed)
#define BB 32
#define SS 4096
#define HH 512
#define AA 256

#define TM 128              // rows per CTA
#define KC 64               // K per chunk
#define NCH (HH / KC)       // 8 chunks

// ---------------- scratch (no allocs allowed) ----------------
__device__ float g_scores[BB * SS];
__device__ float g_decp[BB * AA];
__device__ float g_ctx_part[BB * 32 * HH];
// W_enc^T split to bf16 hi/lo, [n=256][k=512] row-major (k contiguous)
__device__ __nv_bfloat16 g_Bh[AA * HH];
__device__ __nv_bfloat16 g_Bl[AA * HH];

// ---------------- helpers ----------------
__device__ __forceinline__ uint32_t smem_u32(const void* p) {
    uint32_t a;
    asm("{ .reg .u64 t; cvta.to.shared.u64 t, %1; cvt.u32.u64 %0, t; }"
        : "=r"(a) : "l"(p));
    return a;
}

__device__ __forceinline__ float fast_tanh(float x) {
    x = fminf(15.0f, fmaxf(-15.0f, x));
    float t = __expf(2.0f * x);
    return __fdividef(t - 1.0f, t + 1.0f);
}

__device__ __forceinline__ void ldm_x4(uint32_t* r, uint32_t addr) {
    asm volatile("ldmatrix.sync.aligned.m8n8.x4.shared.b16 {%0,%1,%2,%3}, [%4];"
                 : "=r"(r[0]), "=r"(r[1]), "=r"(r[2]), "=r"(r[3]) : "r"(addr));
}

__device__ __forceinline__ void mma16816(float* d, const uint32_t* a, const uint32_t* b) {
    asm volatile(
        "mma.sync.aligned.m16n8k16.row.col.f32.bf16.bf16.f32 "
        "{%0,%1,%2,%3}, {%4,%5,%6,%7}, {%8,%9}, {%0,%1,%2,%3};"
        : "+f"(d[0]), "+f"(d[1]), "+f"(d[2]), "+f"(d[3])
        : "r"(a[0]), "r"(a[1]), "r"(a[2]), "r"(a[3]), "r"(b[0]), "r"(b[1]));
}

#define CP16(dst, src) \
    asm volatile("cp.async.ca.shared.global [%0], [%1], 16;" :: "r"(dst), "l"(src) : "memory")
#define CP_COMMIT() asm volatile("cp.async.commit_group;" ::: "memory")
#define CP_WAIT0()  asm volatile("cp.async.wait_group 0;"  ::: "memory")
#define CP_WAIT1()  asm volatile("cp.async.wait_group 1;"  ::: "memory")

// ---------------------------------------------------------------------------
// prep: W_enc[k][n] -> g_Bh/g_Bl[n][k] bf16 hi/lo. grid(HH), block(AA).
// ---------------------------------------------------------------------------
__global__ void prep_B_kernel(const float* __restrict__ Wenc) {
    int k = blockIdx.x, n = threadIdx.x;
    float v = Wenc[k * AA + n];
    __nv_bfloat16 hi = __float2bfloat16(v);
    __nv_bfloat16 lo = __float2bfloat16(v - __bfloat162float(hi));
    g_Bh[n * HH + k] = hi;
    g_Bl[n * HH + k] = lo;
}

// ---------------------------------------------------------------------------
// k0: dec_p[b][a] = decoder_hidden[b] . W_dec[:,a] + b_dec[a]
// ---------------------------------------------------------------------------
__global__ void dec_proj_kernel(const float* __restrict__ dh,
                                const float* __restrict__ Wdec,
                                const float* __restrict__ bdec) {
    __shared__ float sdh[HH];
    int b = blockIdx.x, t = threadIdx.x;
    for (int k = t; k < HH; k += 256) sdh[k] = dh[b * HH + k];
    __syncthreads();
    float acc = bdec[t];
    #pragma unroll 8
    for (int k = 0; k < HH; k++) acc = fmaf(sdh[k], Wdec[k * AA + t], acc);
    g_decp[b * AA + t] = acc;
}

// ---------------------------------------------------------------------------
// k1: scores via mma.sync split-bf16; B double-buffered via cp.async groups
// (zero register cost); A load+convert serial as in R5 (proven no-spill).
// grid(1024), block(512). CTA tile 128x256, warp grid 4(M)x4(N).
// ---------------------------------------------------------------------------
#define RSTRIDE 144
#define AHALF   (128u * RSTRIDE)            // 18432
#define ABUF    (2u * AHALF)                // 36864 (hi + lo)
#define BHALF   (256u * RSTRIDE)            // 36864
#define BBUF    (2u * BHALF)                // 73728 (hi + lo)
#define SM_A    0u
#define SM_B0   ABUF                        // 36864
#define SM_B1   (SM_B0 + BBUF)              // 110592
#define SM_BIAS (SM_B1 + BBUF)              // 184320
#define SM_WE   (SM_BIAS + 1024u)
#define SM_RED  (SM_WE + 1024u)
#define SM_TOT  (SM_RED + 2048u)            // 188416 bytes

__global__ __launch_bounds__(512) void scores_mma_kernel(
    const float* __restrict__ enc,
    const float* __restrict__ benc,
    const float* __restrict__ We) {

    extern __shared__ char smem[];
    const uint32_t sb = smem_u32(smem);
    const int tid  = threadIdx.x;
    const int wid  = tid >> 5;
    const int lane = tid & 31;
    const int wm = (wid & 3) * 32;
    const int wn = (wid >> 2) * 64;
    const int row0 = blockIdx.x * TM;       // 128 | 4096 -> never crosses batch
    const int batch = row0 / SS;

    float* sbias = (float*)(smem + SM_BIAS);
    float* swe   = (float*)(smem + SM_WE);
    float* red   = (float*)(smem + SM_RED);
    if (tid < AA) {
        sbias[tid] = benc[tid] + g_decp[batch * AA + tid];
        swe[tid]   = We[tid];
    }

    float acc[2][8][4];
    #pragma unroll
    for (int mt = 0; mt < 2; mt++)
        #pragma unroll
        for (int nt = 0; nt < 8; nt++)
            #pragma unroll
            for (int q = 0; q < 4; q++) acc[mt][nt][q] = 0.0f;

    // ldmatrix lane addressing
    const int a_r = (lane & 7) + ((lane >> 3) & 1) * 8;
    const int a_k = (lane >> 4) * 8;
    const int b_n = (lane & 7) + (lane >> 4) * 8;
    const int b_k = ((lane >> 3) & 1) * 8;

    auto issue_B = [&](int c, uint32_t bbase) {
        const char* bh = (const char*)g_Bh;
        const char* bl = (const char*)g_Bl;
        #pragma unroll
        for (int i = 0; i < 4; i++) {
            int idx = tid + i * 512;            // 0..2047
            int n   = idx >> 3;
            int ch  = idx & 7;
            size_t src = (size_t)(n * HH + c * KC + ch * 8) * 2;
            uint32_t dst = n * RSTRIDE + ch * 16;
            CP16(bbase + dst, bh + src);
            CP16(bbase + BHALF + dst, bl + src);
        }
    };

    // prologue: B chunk 0 in flight
    issue_B(0, sb + SM_B0);
    CP_COMMIT();

    for (int c = 0; c < NCH; c++) {
        const uint32_t curB = sb + ((c & 1) ? SM_B1 : SM_B0);
        const uint32_t nxtB = sb + ((c & 1) ? SM_B0 : SM_B1);

        // ---- A: load fp32, split hi/lo, store (short register lifetime) ----
        {
            const float* Ab = enc + (size_t)row0 * HH + c * KC;
            #pragma unroll
            for (int i = 0; i < 4; i++) {
                int idx = tid + i * 512;        // 0..2047 float4s
                int m   = idx >> 4;
                int k4  = (idx & 15) * 4;
                float4 w = *(const float4*)(Ab + (size_t)m * HH + k4);
                __nv_bfloat162 h01 = __floats2bfloat162_rn(w.x, w.y);
                __nv_bfloat162 h23 = __floats2bfloat162_rn(w.z, w.w);
                __nv_bfloat162 l01 = __floats2bfloat162_rn(
                    w.x - __bfloat162float(h01.x), w.y - __bfloat162float(h01.y));
                __nv_bfloat162 l23 = __floats2bfloat162_rn(
                    w.z - __bfloat162float(h23.x), w.w - __bfloat162float(h23.y));
                uint32_t off = m * RSTRIDE + k4 * 2;
                *(uint2*)(smem + SM_A + off) = make_uint2(*(uint32_t*)&h01, *(uint32_t*)&h23);
                *(uint2*)(smem + SM_A + AHALF + off) = make_uint2(*(uint32_t*)&l01, *(uint32_t*)&l23);
            }
        }

        // ---- prefetch next B, then wait for current B only ----
        if (c + 1 < NCH) {
            issue_B(c + 1, nxtB);
            CP_COMMIT();
            CP_WAIT1();          // current chunk's group done; next still flying
        } else {
            CP_WAIT0();          // last chunk: drain
        }
        __syncthreads();

        // ---- compute chunk c: 4 ksteps of 16 ----
        #pragma unroll
        for (int ks = 0; ks < 4; ks++) {
            const int k0 = ks * 16;
            uint32_t ah[2][4], al[2][4];
            #pragma unroll
            for (int mt = 0; mt < 2; mt++) {
                uint32_t ra = (wm + mt * 16 + a_r) * RSTRIDE + (k0 + a_k) * 2;
                ldm_x4(ah[mt], sb + SM_A + ra);
                ldm_x4(al[mt], sb + SM_A + AHALF + ra);
            }
            #pragma unroll
            for (int ntp = 0; ntp < 4; ntp++) {
                uint32_t rb = (wn + ntp * 16 + b_n) * RSTRIDE + (k0 + b_k) * 2;
                uint32_t bh[4], bl[4];
                ldm_x4(bh, curB + rb);
                ldm_x4(bl, curB + BHALF + rb);
                #pragma unroll
                for (int mt = 0; mt < 2; mt++)
                    #pragma unroll
                    for (int h = 0; h < 2; h++) {
                        float* d = acc[mt][ntp * 2 + h];
                        mma16816(d, ah[mt], &bh[h * 2]);   // hi*hi
                        mma16816(d, ah[mt], &bl[h * 2]);   // hi*lo
                        mma16816(d, al[mt], &bh[h * 2]);   // lo*hi
                    }
            }
        }
        __syncthreads();   // A buffer reused next iteration
    }

    // ---- fused epilogue: tanh(+bias)*We, reduce over 256 cols ----
    const int wnidx = wid >> 2;
    #pragma unroll
    for (int mt = 0; mt < 2; mt++) {
        int r_lo = wm + mt * 16 + (lane >> 2);
        float s0 = 0.0f, s1 = 0.0f;
        #pragma unroll
        for (int nt = 0; nt < 8; nt++) {
            int col = wn + nt * 8 + (lane & 3) * 2;
            float w0 = swe[col], w1 = swe[col + 1];
            float bb0 = sbias[col], bb1 = sbias[col + 1];
            s0 = fmaf(fast_tanh(acc[mt][nt][0] + bb0), w0, s0);
            s0 = fmaf(fast_tanh(acc[mt][nt][1] + bb1), w1, s0);
            s1 = fmaf(fast_tanh(acc[mt][nt][2] + bb0), w0, s1);
            s1 = fmaf(fast_tanh(acc[mt][nt][3] + bb1), w1, s1);
        }
        s0 += __shfl_xor_sync(0xffffffffu, s0, 1);
        s0 += __shfl_xor_sync(0xffffffffu, s0, 2);
        s1 += __shfl_xor_sync(0xffffffffu, s1, 1);
        s1 += __shfl_xor_sync(0xffffffffu, s1, 2);
        if ((lane & 3) == 0) {
            red[r_lo * 4 + wnidx]       = s0;
            red[(r_lo + 8) * 4 + wnidx] = s1;
        }
    }
    __syncthreads();
    if (tid < TM) {
        const float* rp = red + tid * 4;
        g_scores[row0 + tid] = rp[0] + rp[1] + rp[2] + rp[3];  // b_e omitted
    }
}

// ---------------------------------------------------------------------------
// k2: softmax over S per batch. grid(B), block(1024). Writes attn to d_out.
// ---------------------------------------------------------------------------
__global__ __launch_bounds__(1024) void softmax_kernel(float* __restrict__ attn_out) {
    __shared__ float sv[SS];
    __shared__ float red[32];
    int b = blockIdx.x, t = threadIdx.x;
    int warp = t >> 5, lane = t & 31;

    float m = -1e30f;
    #pragma unroll
    for (int i = t; i < SS; i += 1024) {
        float v = g_scores[b * SS + i];
        sv[i] = v;
        m = fmaxf(m, v);
    }
    #pragma unroll
    for (int off = 16; off > 0; off >>= 1)
        m = fmaxf(m, __shfl_down_sync(0xffffffffu, m, off));
    if (lane == 0) red[warp] = m;
    __syncthreads();
    if (t == 0) {
        float mm = red[0];
        #pragma unroll
        for (int w = 1; w < 32; w++) mm = fmaxf(mm, red[w]);
        red[0] = mm;
    }
    __syncthreads();
    m = red[0];
    __syncthreads();

    float sum = 0.0f;
    #pragma unroll
    for (int i = t; i < SS; i += 1024) {
        float e = __expf(sv[i] - m);
        sv[i] = e;
        sum += e;
    }
    #pragma unroll
    for (int off = 16; off > 0; off >>= 1)
        sum += __shfl_down_sync(0xffffffffu, sum, off);
    if (lane == 0) red[warp] = sum;
    __syncthreads();
    if (t == 0) {
        float ss = 0.0f;
        #pragma unroll
        for (int w = 0; w < 32; w++) ss += red[w];
        red[0] = 1.0f / ss;
    }
    __syncthreads();
    float inv = red[0];
    #pragma unroll
    for (int i = t; i < SS; i += 1024)
        attn_out[b * SS + i] = sv[i] * inv;
}

// ---------------------------------------------------------------------------
// k3/k4: context, deterministic 2-stage
// ---------------------------------------------------------------------------
__global__ void context_partial_kernel(const float* __restrict__ enc,
                                       const float* __restrict__ attn) {
    __shared__ float sa[128];
    int b  = blockIdx.y;
    int s0 = blockIdx.x * 128;
    int h  = threadIdx.x;
    if (h < 128) sa[h] = attn[b * SS + s0 + h];
    __syncthreads();
    const float* base = enc + ((size_t)b * SS + s0) * HH + h;
    float acc = 0.0f;
    #pragma unroll 16
    for (int s = 0; s < 128; s++)
        acc = fmaf(sa[s], base[(size_t)s * HH], acc);
    g_ctx_part[(b * 32 + blockIdx.x) * HH + h] = acc;
}

__global__ void context_reduce_kernel(float* __restrict__ ctx_out) {
    int b = blockIdx.x, h = threadIdx.x;
    float acc = 0.0f;
    #pragma unroll
    for (int sc = 0; sc < 32; sc++)
        acc += g_ctx_part[(b * 32 + sc) * HH + h];
    ctx_out[b * HH + h] = acc;
}

// ---------------------------------------------------------------------------
// entry point
// ---------------------------------------------------------------------------
extern "C" void kernel_launch(void* const* d_in, const int* in_sizes, int n_in,
                              void* d_out, int out_size) {
    const float* enc  = (const float*)d_in[0];
    const float* dh   = (const float*)d_in[1];
    const float* Wenc = (const float*)d_in[2];
    const float* benc = (const float*)d_in[3];
    const float* Wdec = (const float*)d_in[4];
    const float* bdec = (const float*)d_in[5];
    const float* We   = (const float*)d_in[6];

    float* ctx_out  = (float*)d_out;             // [B, H]
    float* attn_out = (float*)d_out + BB * HH;   // [B, S]

    cudaFuncSetAttribute(scores_mma_kernel,
                         cudaFuncAttributeMaxDynamicSharedMemorySize, SM_TOT);

    prep_B_kernel<<<HH, AA>>>(Wenc);
    dec_proj_kernel<<<BB, 256>>>(dh, Wdec, bdec);
    scores_mma_kernel<<<(BB * SS) / TM, 512, SM_TOT>>>(enc, benc, We);
    softmax_kernel<<<BB, 1024>>>(attn_out);
    context_partial_kernel<<<dim3(32, BB), HH>>>(enc, attn_out);
    context_reduce_kernel<<<BB, HH>>>(ctx_out);
}

// round 10
// speedup vs baseline: 1.2814x; 1.2141x over previous
#include <cuda_runtime.h>
#include <cuda_fp16.h>
#include <cstdint>

// Problem shape (fixed)
#define BB 32
#define SS 4096
#define HH 512
#define AA 256

#define TM 128              // rows per CTA
#define KC 64               // K per chunk
#define NCH (HH / KC)       // 8 chunks

// ---------------- scratch (no allocs allowed) ----------------
__device__ float g_scores[BB * SS];
__device__ float g_decp[BB * AA];
__device__ float g_ctx_part[BB * 32 * HH];
// W_enc^T split to fp16 hi/lo, [n=256][k=512] row-major (k contiguous)
__device__ __half g_Bh[AA * HH];
__device__ __half g_Bl[AA * HH];

// ---------------- helpers ----------------
__device__ __forceinline__ uint32_t smem_u32(const void* p) {
    uint32_t a;
    asm("{ .reg .u64 t; cvta.to.shared.u64 t, %1; cvt.u32.u64 %0, t; }"
        : "=r"(a) : "l"(p));
    return a;
}

__device__ __forceinline__ float fast_tanh(float x) {
    x = fminf(15.0f, fmaxf(-15.0f, x));
    float t = __expf(2.0f * x);
    return __fdividef(t - 1.0f, t + 1.0f);
}

__device__ __forceinline__ void ldm_x4(uint32_t* r, uint32_t addr) {
    asm volatile("ldmatrix.sync.aligned.m8n8.x4.shared.b16 {%0,%1,%2,%3}, [%4];"
                 : "=r"(r[0]), "=r"(r[1]), "=r"(r[2]), "=r"(r[3]) : "r"(addr));
}

__device__ __forceinline__ void mma16816h(float* d, const uint32_t* a, const uint32_t* b) {
    asm volatile(
        "mma.sync.aligned.m16n8k16.row.col.f32.f16.f16.f32 "
        "{%0,%1,%2,%3}, {%4,%5,%6,%7}, {%8,%9}, {%0,%1,%2,%3};"
        : "+f"(d[0]), "+f"(d[1]), "+f"(d[2]), "+f"(d[3])
        : "r"(a[0]), "r"(a[1]), "r"(a[2]), "r"(a[3]), "r"(b[0]), "r"(b[1]));
}

#define CP16(dst, src) \
    asm volatile("cp.async.ca.shared.global [%0], [%1], 16;" :: "r"(dst), "l"(src) : "memory")
#define CP_COMMIT() asm volatile("cp.async.commit_group;" ::: "memory")
#define CP_WAIT0()  asm volatile("cp.async.wait_group 0;"  ::: "memory")
#define CP_WAIT1()  asm volatile("cp.async.wait_group 1;"  ::: "memory")

// ---------------------------------------------------------------------------
// prep: W_enc[k][n] -> g_Bh/g_Bl[n][k] fp16 hi/lo. grid(HH), block(AA).
// ---------------------------------------------------------------------------
__global__ void prep_B_kernel(const float* __restrict__ Wenc) {
    int k = blockIdx.x, n = threadIdx.x;
    float v = Wenc[k * AA + n];
    __half hi = __float2half(v);
    __half lo = __float2half(v - __half2float(hi));  // subnormal fp16: ok, tensor cores handle
    g_Bh[n * HH + k] = hi;
    g_Bl[n * HH + k] = lo;
}

// ---------------------------------------------------------------------------
// k0: dec_p[b][a] = decoder_hidden[b] . W_dec[:,a] + b_dec[a]
// ---------------------------------------------------------------------------
__global__ void dec_proj_kernel(const float* __restrict__ dh,
                                const float* __restrict__ Wdec,
                                const float* __restrict__ bdec) {
    __shared__ float sdh[HH];
    int b = blockIdx.x, t = threadIdx.x;
    for (int k = t; k < HH; k += 256) sdh[k] = dh[b * HH + k];
    __syncthreads();
    float acc = bdec[t];
    #pragma unroll 8
    for (int k = 0; k < HH; k++) acc = fmaf(sdh[k], Wdec[k * AA + t], acc);
    g_decp[b * AA + t] = acc;
}

// ---------------------------------------------------------------------------
// k1: scores via mma.sync fp16 2-term (A single fp16, B = hi+lo fp16).
// B double-buffered via cp.async groups. grid(1024), block(512).
// CTA tile 128x256, warp grid 4(M)x4(N), warp tile 32x64.
// ---------------------------------------------------------------------------
#define RSTRIDE 144
#define ABUF    (128u * RSTRIDE)            // 18432 (single fp16 A)
#define BHALF   (256u * RSTRIDE)            // 36864
#define BBUF    (2u * BHALF)                // 73728 (hi + lo)
#define SM_A    0u
#define SM_B0   ABUF                        // 18432
#define SM_B1   (SM_B0 + BBUF)              // 92160
#define SM_BIAS (SM_B1 + BBUF)              // 165888
#define SM_WE   (SM_BIAS + 1024u)
#define SM_RED  (SM_WE + 1024u)
#define SM_TOT  (SM_RED + 2048u)            // 169984 bytes

__global__ __launch_bounds__(512) void scores_mma_kernel(
    const float* __restrict__ enc,
    const float* __restrict__ benc,
    const float* __restrict__ We) {

    extern __shared__ char smem[];
    const uint32_t sb = smem_u32(smem);
    const int tid  = threadIdx.x;
    const int wid  = tid >> 5;
    const int lane = tid & 31;
    const int wm = (wid & 3) * 32;
    const int wn = (wid >> 2) * 64;
    const int row0 = blockIdx.x * TM;       // 128 | 4096 -> never crosses batch
    const int batch = row0 / SS;

    float* sbias = (float*)(smem + SM_BIAS);
    float* swe   = (float*)(smem + SM_WE);
    float* red   = (float*)(smem + SM_RED);
    if (tid < AA) {
        sbias[tid] = benc[tid] + g_decp[batch * AA + tid];
        swe[tid]   = We[tid];
    }

    float acc[2][8][4];
    #pragma unroll
    for (int mt = 0; mt < 2; mt++)
        #pragma unroll
        for (int nt = 0; nt < 8; nt++)
            #pragma unroll
            for (int q = 0; q < 4; q++) acc[mt][nt][q] = 0.0f;

    // ldmatrix lane addressing
    const int a_r = (lane & 7) + ((lane >> 3) & 1) * 8;
    const int a_k = (lane >> 4) * 8;
    const int b_n = (lane & 7) + (lane >> 4) * 8;
    const int b_k = ((lane >> 3) & 1) * 8;

    auto issue_B = [&](int c, uint32_t bbase) {
        const char* bh = (const char*)g_Bh;
        const char* bl = (const char*)g_Bl;
        #pragma unroll
        for (int i = 0; i < 4; i++) {
            int idx = tid + i * 512;            // 0..2047
            int n   = idx >> 3;
            int ch  = idx & 7;
            size_t src = (size_t)(n * HH + c * KC + ch * 8) * 2;
            uint32_t dst = n * RSTRIDE + ch * 16;
            CP16(bbase + dst, bh + src);
            CP16(bbase + BHALF + dst, bl + src);
        }
    };

    // prologue: B chunk 0 in flight
    issue_B(0, sb + SM_B0);
    CP_COMMIT();

    for (int c = 0; c < NCH; c++) {
        const uint32_t curB = sb + ((c & 1) ? SM_B1 : SM_B0);
        const uint32_t nxtB = sb + ((c & 1) ? SM_B0 : SM_B1);

        // ---- A: load fp32, convert to single fp16, store ----
        {
            const float* Ab = enc + (size_t)row0 * HH + c * KC;
            #pragma unroll
            for (int i = 0; i < 4; i++) {
                int idx = tid + i * 512;        // 0..2047 float4s
                int m   = idx >> 4;
                int k4  = (idx & 15) * 4;
                float4 w = *(const float4*)(Ab + (size_t)m * HH + k4);
                __half2 h01 = __floats2half2_rn(w.x, w.y);
                __half2 h23 = __floats2half2_rn(w.z, w.w);
                uint32_t off = m * RSTRIDE + k4 * 2;
                *(uint2*)(smem + SM_A + off) =
                    make_uint2(*(uint32_t*)&h01, *(uint32_t*)&h23);
            }
        }

        // ---- prefetch next B, wait for current B only ----
        if (c + 1 < NCH) {
            issue_B(c + 1, nxtB);
            CP_COMMIT();
            CP_WAIT1();
        } else {
            CP_WAIT0();
        }
        __syncthreads();

        // ---- compute chunk c: 4 ksteps of 16 ----
        #pragma unroll
        for (int ks = 0; ks < 4; ks++) {
            const int k0 = ks * 16;
            uint32_t ah[2][4];
            #pragma unroll
            for (int mt = 0; mt < 2; mt++) {
                uint32_t ra = (wm + mt * 16 + a_r) * RSTRIDE + (k0 + a_k) * 2;
                ldm_x4(ah[mt], sb + SM_A + ra);
            }
            #pragma unroll
            for (int ntp = 0; ntp < 4; ntp++) {
                uint32_t rb = (wn + ntp * 16 + b_n) * RSTRIDE + (k0 + b_k) * 2;
                uint32_t bh[4], bl[4];
                ldm_x4(bh, curB + rb);
                ldm_x4(bl, curB + BHALF + rb);
                #pragma unroll
                for (int mt = 0; mt < 2; mt++)
                    #pragma unroll
                    for (int h = 0; h < 2; h++) {
                        float* d = acc[mt][ntp * 2 + h];
                        mma16816h(d, ah[mt], &bh[h * 2]);   // A*B_hi
                        mma16816h(d, ah[mt], &bl[h * 2]);   // A*B_lo
                    }
            }
        }
        __syncthreads();   // A buffer reused next iteration
    }

    // ---- fused epilogue: tanh(+bias)*We, reduce over 256 cols ----
    const int wnidx = wid >> 2;
    #pragma unroll
    for (int mt = 0; mt < 2; mt++) {
        int r_lo = wm + mt * 16 + (lane >> 2);
        float s0 = 0.0f, s1 = 0.0f;
        #pragma unroll
        for (int nt = 0; nt < 8; nt++) {
            int col = wn + nt * 8 + (lane & 3) * 2;
            float w0 = swe[col], w1 = swe[col + 1];
            float bb0 = sbias[col], bb1 = sbias[col + 1];
            s0 = fmaf(fast_tanh(acc[mt][nt][0] + bb0), w0, s0);
            s0 = fmaf(fast_tanh(acc[mt][nt][1] + bb1), w1, s0);
            s1 = fmaf(fast_tanh(acc[mt][nt][2] + bb0), w0, s1);
            s1 = fmaf(fast_tanh(acc[mt][nt][3] + bb1), w1, s1);
        }
        s0 += __shfl_xor_sync(0xffffffffu, s0, 1);
        s0 += __shfl_xor_sync(0xffffffffu, s0, 2);
        s1 += __shfl_xor_sync(0xffffffffu, s1, 1);
        s1 += __shfl_xor_sync(0xffffffffu, s1, 2);
        if ((lane & 3) == 0) {
            red[r_lo * 4 + wnidx]       = s0;
            red[(r_lo + 8) * 4 + wnidx] = s1;
        }
    }
    __syncthreads();
    if (tid < TM) {
        const float* rp = red + tid * 4;
        g_scores[row0 + tid] = rp[0] + rp[1] + rp[2] + rp[3];  // b_e omitted
    }
}

// ---------------------------------------------------------------------------
// k2: softmax over S per batch. grid(B), block(1024). Writes attn to d_out.
// ---------------------------------------------------------------------------
__global__ __launch_bounds__(1024) void softmax_kernel(float* __restrict__ attn_out) {
    __shared__ float sv[SS];
    __shared__ float red[32];
    int b = blockIdx.x, t = threadIdx.x;
    int warp = t >> 5, lane = t & 31;

    float m = -1e30f;
    #pragma unroll
    for (int i = t; i < SS; i += 1024) {
        float v = g_scores[b * SS + i];
        sv[i] = v;
        m = fmaxf(m, v);
    }
    #pragma unroll
    for (int off = 16; off > 0; off >>= 1)
        m = fmaxf(m, __shfl_down_sync(0xffffffffu, m, off));
    if (lane == 0) red[warp] = m;
    __syncthreads();
    if (t == 0) {
        float mm = red[0];
        #pragma unroll
        for (int w = 1; w < 32; w++) mm = fmaxf(mm, red[w]);
        red[0] = mm;
    }
    __syncthreads();
    m = red[0];
    __syncthreads();

    float sum = 0.0f;
    #pragma unroll
    for (int i = t; i < SS; i += 1024) {
        float e = __expf(sv[i] - m);
        sv[i] = e;
        sum += e;
    }
    #pragma unroll
    for (int off = 16; off > 0; off >>= 1)
        sum += __shfl_down_sync(0xffffffffu, sum, off);
    if (lane == 0) red[warp] = sum;
    __syncthreads();
    if (t == 0) {
        float ss = 0.0f;
        #pragma unroll
        for (int w = 0; w < 32; w++) ss += red[w];
        red[0] = 1.0f / ss;
    }
    __syncthreads();
    float inv = red[0];
    #pragma unroll
    for (int i = t; i < SS; i += 1024)
        attn_out[b * SS + i] = sv[i] * inv;
}

// ---------------------------------------------------------------------------
// k3: context partials, float4 per thread. grid(32, B), block(128).
// ---------------------------------------------------------------------------
__global__ void context_partial_kernel(const float* __restrict__ enc,
                                       const float* __restrict__ attn) {
    __shared__ float sa[128];
    int b  = blockIdx.y;
    int s0 = blockIdx.x * 128;
    int t  = threadIdx.x;           // 0..127, owns h = 4t..4t+3
    sa[t] = attn[b * SS + s0 + t];
    __syncthreads();
    const float* base = enc + ((size_t)b * SS + s0) * HH + t * 4;
    float4 acc = make_float4(0.f, 0.f, 0.f, 0.f);
    #pragma unroll 8
    for (int s = 0; s < 128; s++) {
        float4 v = *(const float4*)(base + (size_t)s * HH);
        float w = sa[s];
        acc.x = fmaf(w, v.x, acc.x);
        acc.y = fmaf(w, v.y, acc.y);
        acc.z = fmaf(w, v.z, acc.z);
        acc.w = fmaf(w, v.w, acc.w);
    }
    *(float4*)&g_ctx_part[(b * 32 + blockIdx.x) * HH + t * 4] = acc;
}

__global__ void context_reduce_kernel(float* __restrict__ ctx_out) {
    int b = blockIdx.x, h = threadIdx.x;
    float acc = 0.0f;
    #pragma unroll
    for (int sc = 0; sc < 32; sc++)
        acc += g_ctx_part[(b * 32 + sc) * HH + h];
    ctx_out[b * HH + h] = acc;
}

// ---------------------------------------------------------------------------
// entry point
// ---------------------------------------------------------------------------
extern "C" void kernel_launch(void* const* d_in, const int* in_sizes, int n_in,
                              void* d_out, int out_size) {
    const float* enc  = (const float*)d_in[0];
    const float* dh   = (const float*)d_in[1];
    const float* Wenc = (const float*)d_in[2];
    const float* benc = (const float*)d_in[3];
    const float* Wdec = (const float*)d_in[4];
    const float* bdec = (const float*)d_in[5];
    const float* We   = (const float*)d_in[6];

    float* ctx_out  = (float*)d_out;             // [B, H]
    float* attn_out = (float*)d_out + BB * HH;   // [B, S]

    cudaFuncSetAttribute(scores_mma_kernel,
                         cudaFuncAttributeMaxDynamicSharedMemorySize, SM_TOT);

    prep_B_kernel<<<HH, AA>>>(Wenc);
    dec_proj_kernel<<<BB, 256>>>(dh, Wdec, bdec);
    scores_mma_kernel<<<(BB * SS) / TM, 512, SM_TOT>>>(enc, benc, We);
    softmax_kernel<<<BB, 1024>>>(attn_out);
    context_partial_kernel<<<dim3(32, BB), 128>>>(enc, attn_out);
    context_reduce_kernel<<<BB, HH>>>(ctx_out);
}

// round 11
// speedup vs baseline: 1.6702x; 1.3034x over previous
#include <cuda_runtime.h>
#include <cuda_fp16.h>
#include <cstdint>

// Problem shape (fixed)
#define BB 32
#define SS 4096
#define HH 512
#define AA 256

#define TM 128              // rows per CTA
#define KC 64               // K per chunk
#define NCH (HH / KC)       // 8 chunks

// ---------------- scratch (no allocs allowed) ----------------
__device__ float g_scores[BB * SS];
__device__ float g_decp[BB * AA];
__device__ float g_ctx_part[BB * 32 * HH];
// W_enc^T as fp16, [n=256][k=512] row-major (k contiguous)
__device__ __half g_Bh[AA * HH];

// ---------------- helpers ----------------
__device__ __forceinline__ uint32_t smem_u32(const void* p) {
    uint32_t a;
    asm("{ .reg .u64 t; cvta.to.shared.u64 t, %1; cvt.u32.u64 %0, t; }"
        : "=r"(a) : "l"(p));
    return a;
}

__device__ __forceinline__ float fast_tanh(float x) {
    x = fminf(15.0f, fmaxf(-15.0f, x));
    float t = __expf(2.0f * x);
    return __fdividef(t - 1.0f, t + 1.0f);
}

__device__ __forceinline__ void ldm_x4(uint32_t* r, uint32_t addr) {
    asm volatile("ldmatrix.sync.aligned.m8n8.x4.shared.b16 {%0,%1,%2,%3}, [%4];"
                 : "=r"(r[0]), "=r"(r[1]), "=r"(r[2]), "=r"(r[3]) : "r"(addr));
}

__device__ __forceinline__ void mma16816h(float* d, const uint32_t* a, const uint32_t* b) {
    asm volatile(
        "mma.sync.aligned.m16n8k16.row.col.f32.f16.f16.f32 "
        "{%0,%1,%2,%3}, {%4,%5,%6,%7}, {%8,%9}, {%0,%1,%2,%3};"
        : "+f"(d[0]), "+f"(d[1]), "+f"(d[2]), "+f"(d[3])
        : "r"(a[0]), "r"(a[1]), "r"(a[2]), "r"(a[3]), "r"(b[0]), "r"(b[1]));
}

#define CP16(dst, src) \
    asm volatile("cp.async.ca.shared.global [%0], [%1], 16;" :: "r"(dst), "l"(src) : "memory")
#define CP_COMMIT() asm volatile("cp.async.commit_group;" ::: "memory")
#define CP_WAIT0()  asm volatile("cp.async.wait_group 0;"  ::: "memory")
#define CP_WAIT1()  asm volatile("cp.async.wait_group 1;"  ::: "memory")

// ---------------------------------------------------------------------------
// prep: W_enc[k][n] -> g_Bh[n][k] fp16. grid(HH), block(AA).
// ---------------------------------------------------------------------------
__global__ void prep_B_kernel(const float* __restrict__ Wenc) {
    int k = blockIdx.x, n = threadIdx.x;
    g_Bh[n * HH + k] = __float2half(Wenc[k * AA + n]);
}

// ---------------------------------------------------------------------------
// k0: dec_p[b][a] = decoder_hidden[b] . W_dec[:,a] + b_dec[a]
// ---------------------------------------------------------------------------
__global__ void dec_proj_kernel(const float* __restrict__ dh,
                                const float* __restrict__ Wdec,
                                const float* __restrict__ bdec) {
    __shared__ float sdh[HH];
    int b = blockIdx.x, t = threadIdx.x;
    for (int k = t; k < HH; k += 256) sdh[k] = dh[b * HH + k];
    __syncthreads();
    float acc = bdec[t];
    #pragma unroll 8
    for (int k = 0; k < HH; k++) acc = fmaf(sdh[k], Wdec[k * AA + t], acc);
    g_decp[b * AA + t] = acc;
}

// ---------------------------------------------------------------------------
// k1: scores via mma.sync pure fp16 (A fp16, B fp16). B double-buffered via
// cp.async groups. grid(1024), block(512). CTA tile 128x256, warp 4(M)x4(N).
// smem ~96 KB -> 2 CTAs/SM (cross-CTA overlap of load vs MMA).
// ---------------------------------------------------------------------------
#define RSTRIDE 144
#define ABUF    (128u * RSTRIDE)            // 18432 (fp16 A)
#define BBUF    (256u * RSTRIDE)            // 36864 (fp16 B)
#define SM_A    0u
#define SM_B0   ABUF                        // 18432
#define SM_B1   (SM_B0 + BBUF)              // 55296
#define SM_BIAS (SM_B1 + BBUF)              // 92160
#define SM_WE   (SM_BIAS + 1024u)
#define SM_RED  (SM_WE + 1024u)
#define SM_TOT  (SM_RED + 2048u)            // 96256 bytes

__global__ __launch_bounds__(512) void scores_mma_kernel(
    const float* __restrict__ enc,
    const float* __restrict__ benc,
    const float* __restrict__ We) {

    extern __shared__ char smem[];
    const uint32_t sb = smem_u32(smem);
    const int tid  = threadIdx.x;
    const int wid  = tid >> 5;
    const int lane = tid & 31;
    const int wm = (wid & 3) * 32;
    const int wn = (wid >> 2) * 64;
    const int row0 = blockIdx.x * TM;       // 128 | 4096 -> never crosses batch
    const int batch = row0 / SS;

    float* sbias = (float*)(smem + SM_BIAS);
    float* swe   = (float*)(smem + SM_WE);
    float* red   = (float*)(smem + SM_RED);
    if (tid < AA) {
        sbias[tid] = benc[tid] + g_decp[batch * AA + tid];
        swe[tid]   = We[tid];
    }

    float acc[2][8][4];
    #pragma unroll
    for (int mt = 0; mt < 2; mt++)
        #pragma unroll
        for (int nt = 0; nt < 8; nt++)
            #pragma unroll
            for (int q = 0; q < 4; q++) acc[mt][nt][q] = 0.0f;

    // ldmatrix lane addressing
    const int a_r = (lane & 7) + ((lane >> 3) & 1) * 8;
    const int a_k = (lane >> 4) * 8;
    const int b_n = (lane & 7) + (lane >> 4) * 8;
    const int b_k = ((lane >> 3) & 1) * 8;

    auto issue_B = [&](int c, uint32_t bbase) {
        const char* bh = (const char*)g_Bh;
        #pragma unroll
        for (int i = 0; i < 4; i++) {
            int idx = tid + i * 512;            // 0..2047
            int n   = idx >> 3;
            int ch  = idx & 7;
            size_t src = (size_t)(n * HH + c * KC + ch * 8) * 2;
            uint32_t dst = n * RSTRIDE + ch * 16;
            CP16(bbase + dst, bh + src);
        }
    };

    // prologue: B chunk 0 in flight
    issue_B(0, sb + SM_B0);
    CP_COMMIT();

    for (int c = 0; c < NCH; c++) {
        const uint32_t curB = sb + ((c & 1) ? SM_B1 : SM_B0);
        const uint32_t nxtB = sb + ((c & 1) ? SM_B0 : SM_B1);

        // ---- A: load fp32, convert to fp16, store ----
        {
            const float* Ab = enc + (size_t)row0 * HH + c * KC;
            #pragma unroll
            for (int i = 0; i < 4; i++) {
                int idx = tid + i * 512;        // 0..2047 float4s
                int m   = idx >> 4;
                int k4  = (idx & 15) * 4;
                float4 w = *(const float4*)(Ab + (size_t)m * HH + k4);
                __half2 h01 = __floats2half2_rn(w.x, w.y);
                __half2 h23 = __floats2half2_rn(w.z, w.w);
                uint32_t off = m * RSTRIDE + k4 * 2;
                *(uint2*)(smem + SM_A + off) =
                    make_uint2(*(uint32_t*)&h01, *(uint32_t*)&h23);
            }
        }

        // ---- prefetch next B, wait for current B only ----
        if (c + 1 < NCH) {
            issue_B(c + 1, nxtB);
            CP_COMMIT();
            CP_WAIT1();
        } else {
            CP_WAIT0();
        }
        __syncthreads();

        // ---- compute chunk c: 4 ksteps of 16 ----
        #pragma unroll
        for (int ks = 0; ks < 4; ks++) {
            const int k0 = ks * 16;
            uint32_t ah[2][4];
            #pragma unroll
            for (int mt = 0; mt < 2; mt++) {
                uint32_t ra = (wm + mt * 16 + a_r) * RSTRIDE + (k0 + a_k) * 2;
                ldm_x4(ah[mt], sb + SM_A + ra);
            }
            #pragma unroll
            for (int ntp = 0; ntp < 4; ntp++) {
                uint32_t rb = (wn + ntp * 16 + b_n) * RSTRIDE + (k0 + b_k) * 2;
                uint32_t bh[4];
                ldm_x4(bh, curB + rb);
                #pragma unroll
                for (int mt = 0; mt < 2; mt++)
                    #pragma unroll
                    for (int h = 0; h < 2; h++)
                        mma16816h(acc[mt][ntp * 2 + h], ah[mt], &bh[h * 2]);
            }
        }
        __syncthreads();   // A buffer reused next iteration
    }

    // ---- fused epilogue: tanh(+bias)*We, reduce over 256 cols ----
    const int wnidx = wid >> 2;
    #pragma unroll
    for (int mt = 0; mt < 2; mt++) {
        int r_lo = wm + mt * 16 + (lane >> 2);
        float s0 = 0.0f, s1 = 0.0f;
        #pragma unroll
        for (int nt = 0; nt < 8; nt++) {
            int col = wn + nt * 8 + (lane & 3) * 2;
            float w0 = swe[col], w1 = swe[col + 1];
            float bb0 = sbias[col], bb1 = sbias[col + 1];
            s0 = fmaf(fast_tanh(acc[mt][nt][0] + bb0), w0, s0);
            s0 = fmaf(fast_tanh(acc[mt][nt][1] + bb1), w1, s0);
            s1 = fmaf(fast_tanh(acc[mt][nt][2] + bb0), w0, s1);
            s1 = fmaf(fast_tanh(acc[mt][nt][3] + bb1), w1, s1);
        }
        s0 += __shfl_xor_sync(0xffffffffu, s0, 1);
        s0 += __shfl_xor_sync(0xffffffffu, s0, 2);
        s1 += __shfl_xor_sync(0xffffffffu, s1, 1);
        s1 += __shfl_xor_sync(0xffffffffu, s1, 2);
        if ((lane & 3) == 0) {
            red[r_lo * 4 + wnidx]       = s0;
            red[(r_lo + 8) * 4 + wnidx] = s1;
        }
    }
    __syncthreads();
    if (tid < TM) {
        const float* rp = red + tid * 4;
        g_scores[row0 + tid] = rp[0] + rp[1] + rp[2] + rp[3];  // b_e omitted
    }
}

// ---------------------------------------------------------------------------
// k2: softmax over S per batch. grid(B), block(1024). Writes attn to d_out.
// ---------------------------------------------------------------------------
__global__ __launch_bounds__(1024) void softmax_kernel(float* __restrict__ attn_out) {
    __shared__ float sv[SS];
    __shared__ float red[32];
    int b = blockIdx.x, t = threadIdx.x;
    int warp = t >> 5, lane = t & 31;

    float m = -1e30f;
    #pragma unroll
    for (int i = t; i < SS; i += 1024) {
        float v = g_scores[b * SS + i];
        sv[i] = v;
        m = fmaxf(m, v);
    }
    #pragma unroll
    for (int off = 16; off > 0; off >>= 1)
        m = fmaxf(m, __shfl_down_sync(0xffffffffu, m, off));
    if (lane == 0) red[warp] = m;
    __syncthreads();
    if (t == 0) {
        float mm = red[0];
        #pragma unroll
        for (int w = 1; w < 32; w++) mm = fmaxf(mm, red[w]);
        red[0] = mm;
    }
    __syncthreads();
    m = red[0];
    __syncthreads();

    float sum = 0.0f;
    #pragma unroll
    for (int i = t; i < SS; i += 1024) {
        float e = __expf(sv[i] - m);
        sv[i] = e;
        sum += e;
    }
    #pragma unroll
    for (int off = 16; off > 0; off >>= 1)
        sum += __shfl_down_sync(0xffffffffu, sum, off);
    if (lane == 0) red[warp] = sum;
    __syncthreads();
    if (t == 0) {
        float ss = 0.0f;
        #pragma unroll
        for (int w = 0; w < 32; w++) ss += red[w];
        red[0] = 1.0f / ss;
    }
    __syncthreads();
    float inv = red[0];
    #pragma unroll
    for (int i = t; i < SS; i += 1024)
        attn_out[b * SS + i] = sv[i] * inv;
}

// ---------------------------------------------------------------------------
// k3: context partials, float4 per thread. grid(32, B), block(128).
// ---------------------------------------------------------------------------
__global__ void context_partial_kernel(const float* __restrict__ enc,
                                       const float* __restrict__ attn) {
    __shared__ float sa[128];
    int b  = blockIdx.y;
    int s0 = blockIdx.x * 128;
    int t  = threadIdx.x;           // 0..127, owns h = 4t..4t+3
    sa[t] = attn[b * SS + s0 + t];
    __syncthreads();
    const float* base = enc + ((size_t)b * SS + s0) * HH + t * 4;
    float4 acc = make_float4(0.f, 0.f, 0.f, 0.f);
    #pragma unroll 8
    for (int s = 0; s < 128; s++) {
        float4 v = *(const float4*)(base + (size_t)s * HH);
        float w = sa[s];
        acc.x = fmaf(w, v.x, acc.x);
        acc.y = fmaf(w, v.y, acc.y);
        acc.z = fmaf(w, v.z, acc.z);
        acc.w = fmaf(w, v.w, acc.w);
    }
    *(float4*)&g_ctx_part[(b * 32 + blockIdx.x) * HH + t * 4] = acc;
}

__global__ void context_reduce_kernel(float* __restrict__ ctx_out) {
    int b = blockIdx.x, h = threadIdx.x;
    float acc = 0.0f;
    #pragma unroll
    for (int sc = 0; sc < 32; sc++)
        acc += g_ctx_part[(b * 32 + sc) * HH + h];
    ctx_out[b * HH + h] = acc;
}

// ---------------------------------------------------------------------------
// entry point
// ---------------------------------------------------------------------------
extern "C" void kernel_launch(void* const* d_in, const int* in_sizes, int n_in,
                              void* d_out, int out_size) {
    const float* enc  = (const float*)d_in[0];
    const float* dh   = (const float*)d_in[1];
    const float* Wenc = (const float*)d_in[2];
    const float* benc = (const float*)d_in[3];
    const float* Wdec = (const float*)d_in[4];
    const float* bdec = (const float*)d_in[5];
    const float* We   = (const float*)d_in[6];

    float* ctx_out  = (float*)d_out;             // [B, H]
    float* attn_out = (float*)d_out + BB * HH;   // [B, S]

    cudaFuncSetAttribute(scores_mma_kernel,
                         cudaFuncAttributeMaxDynamicSharedMemorySize, SM_TOT);

    prep_B_kernel<<<HH, AA>>>(Wenc);
    dec_proj_kernel<<<BB, 256>>>(dh, Wdec, bdec);
    scores_mma_kernel<<<(BB * SS) / TM, 512, SM_TOT>>>(enc, benc, We);
    softmax_kernel<<<BB, 1024>>>(attn_out);
    context_partial_kernel<<<dim3(32, BB), 128>>>(enc, attn_out);
    context_reduce_kernel<<<BB, HH>>>(ctx_out);
}

// round 12
// speedup vs baseline: 1.7128x; 1.0255x over previous
#include <cuda_runtime.h>
#include <cuda_fp16.h>
#include <cstdint>

// Problem shape (fixed)
#define BB 32
#define SS 4096
#define HH 512
#define AA 256

#define TM 128              // rows per CTA
#define KC 64               // K per chunk
#define NCH (HH / KC)       // 8 chunks

// ---------------- scratch (no allocs allowed) ----------------
__device__ float g_scores[BB * SS];
__device__ float g_decp[BB * AA];
__device__ float g_ctx_part[BB * 32 * HH];
// W_enc^T as fp16, [n=256][k=512] row-major (k contiguous)
__device__ __half g_Bh[AA * HH];
// fp16 copy of encoder_outputs, written by scores kernel (free, MMA-bound)
__device__ __half g_encH[(size_t)BB * SS * HH];   // 134 MB

// ---------------- helpers ----------------
__device__ __forceinline__ uint32_t smem_u32(const void* p) {
    uint32_t a;
    asm("{ .reg .u64 t; cvta.to.shared.u64 t, %1; cvt.u32.u64 %0, t; }"
        : "=r"(a) : "l"(p));
    return a;
}

__device__ __forceinline__ float fast_tanh(float x) {
    x = fminf(15.0f, fmaxf(-15.0f, x));
    float t = __expf(2.0f * x);
    return __fdividef(t - 1.0f, t + 1.0f);
}

__device__ __forceinline__ void ldm_x4(uint32_t* r, uint32_t addr) {
    asm volatile("ldmatrix.sync.aligned.m8n8.x4.shared.b16 {%0,%1,%2,%3}, [%4];"
                 : "=r"(r[0]), "=r"(r[1]), "=r"(r[2]), "=r"(r[3]) : "r"(addr));
}

__device__ __forceinline__ void mma16816h(float* d, const uint32_t* a, const uint32_t* b) {
    asm volatile(
        "mma.sync.aligned.m16n8k16.row.col.f32.f16.f16.f32 "
        "{%0,%1,%2,%3}, {%4,%5,%6,%7}, {%8,%9}, {%0,%1,%2,%3};"
        : "+f"(d[0]), "+f"(d[1]), "+f"(d[2]), "+f"(d[3])
        : "r"(a[0]), "r"(a[1]), "r"(a[2]), "r"(a[3]), "r"(b[0]), "r"(b[1]));
}

#define CP16(dst, src) \
    asm volatile("cp.async.ca.shared.global [%0], [%1], 16;" :: "r"(dst), "l"(src) : "memory")
#define CP_COMMIT() asm volatile("cp.async.commit_group;" ::: "memory")
#define CP_WAIT0()  asm volatile("cp.async.wait_group 0;"  ::: "memory")
#define CP_WAIT1()  asm volatile("cp.async.wait_group 1;"  ::: "memory")

// ---------------------------------------------------------------------------
// prep: W_enc[k][n] -> g_Bh[n][k] fp16. grid(HH), block(AA).
// ---------------------------------------------------------------------------
__global__ void prep_B_kernel(const float* __restrict__ Wenc) {
    int k = blockIdx.x, n = threadIdx.x;
    g_Bh[n * HH + k] = __float2half(Wenc[k * AA + n]);
}

// ---------------------------------------------------------------------------
// k0: dec_p[b][a] = decoder_hidden[b] . W_dec[:,a] + b_dec[a]
// ---------------------------------------------------------------------------
__global__ void dec_proj_kernel(const float* __restrict__ dh,
                                const float* __restrict__ Wdec,
                                const float* __restrict__ bdec) {
    __shared__ float sdh[HH];
    int b = blockIdx.x, t = threadIdx.x;
    for (int k = t; k < HH; k += 256) sdh[k] = dh[b * HH + k];
    __syncthreads();
    float acc = bdec[t];
    #pragma unroll 8
    for (int k = 0; k < HH; k++) acc = fmaf(sdh[k], Wdec[k * AA + t], acc);
    g_decp[b * AA + t] = acc;
}

// ---------------------------------------------------------------------------
// k1: scores via mma.sync pure fp16; also persists A's fp16 conversion to
// g_encH (hidden under MMA-bound mainloop). B double-buffered via cp.async.
// grid(1024), block(512). CTA tile 128x256, warp 4(M)x4(N). ~96 KB smem.
// ---------------------------------------------------------------------------
#define RSTRIDE 144
#define ABUF    (128u * RSTRIDE)            // 18432 (fp16 A)
#define BBUF    (256u * RSTRIDE)            // 36864 (fp16 B)
#define SM_A    0u
#define SM_B0   ABUF                        // 18432
#define SM_B1   (SM_B0 + BBUF)              // 55296
#define SM_BIAS (SM_B1 + BBUF)              // 92160
#define SM_WE   (SM_BIAS + 1024u)
#define SM_RED  (SM_WE + 1024u)
#define SM_TOT  (SM_RED + 2048u)            // 96256 bytes

__global__ __launch_bounds__(512) void scores_mma_kernel(
    const float* __restrict__ enc,
    const float* __restrict__ benc,
    const float* __restrict__ We) {

    extern __shared__ char smem[];
    const uint32_t sb = smem_u32(smem);
    const int tid  = threadIdx.x;
    const int wid  = tid >> 5;
    const int lane = tid & 31;
    const int wm = (wid & 3) * 32;
    const int wn = (wid >> 2) * 64;
    const int row0 = blockIdx.x * TM;       // 128 | 4096 -> never crosses batch
    const int batch = row0 / SS;

    float* sbias = (float*)(smem + SM_BIAS);
    float* swe   = (float*)(smem + SM_WE);
    float* red   = (float*)(smem + SM_RED);
    if (tid < AA) {
        sbias[tid] = benc[tid] + g_decp[batch * AA + tid];
        swe[tid]   = We[tid];
    }

    float acc[2][8][4];
    #pragma unroll
    for (int mt = 0; mt < 2; mt++)
        #pragma unroll
        for (int nt = 0; nt < 8; nt++)
            #pragma unroll
            for (int q = 0; q < 4; q++) acc[mt][nt][q] = 0.0f;

    // ldmatrix lane addressing
    const int a_r = (lane & 7) + ((lane >> 3) & 1) * 8;
    const int a_k = (lane >> 4) * 8;
    const int b_n = (lane & 7) + (lane >> 4) * 8;
    const int b_k = ((lane >> 3) & 1) * 8;

    auto issue_B = [&](int c, uint32_t bbase) {
        const char* bh = (const char*)g_Bh;
        #pragma unroll
        for (int i = 0; i < 4; i++) {
            int idx = tid + i * 512;            // 0..2047
            int n   = idx >> 3;
            int ch  = idx & 7;
            size_t src = (size_t)(n * HH + c * KC + ch * 8) * 2;
            uint32_t dst = n * RSTRIDE + ch * 16;
            CP16(bbase + dst, bh + src);
        }
    };

    // prologue: B chunk 0 in flight
    issue_B(0, sb + SM_B0);
    CP_COMMIT();

    for (int c = 0; c < NCH; c++) {
        const uint32_t curB = sb + ((c & 1) ? SM_B1 : SM_B0);
        const uint32_t nxtB = sb + ((c & 1) ? SM_B0 : SM_B1);

        // ---- A: load fp32, convert to fp16, store to smem AND g_encH ----
        {
            const float* Ab = enc + (size_t)row0 * HH + c * KC;
            __half* Eh = g_encH + (size_t)row0 * HH + c * KC;
            #pragma unroll
            for (int i = 0; i < 4; i++) {
                int idx = tid + i * 512;        // 0..2047 float4s
                int m   = idx >> 4;
                int k4  = (idx & 15) * 4;
                float4 w = *(const float4*)(Ab + (size_t)m * HH + k4);
                __half2 h01 = __floats2half2_rn(w.x, w.y);
                __half2 h23 = __floats2half2_rn(w.z, w.w);
                uint2 packed = make_uint2(*(uint32_t*)&h01, *(uint32_t*)&h23);
                uint32_t off = m * RSTRIDE + k4 * 2;
                *(uint2*)(smem + SM_A + off) = packed;
                *(uint2*)(Eh + (size_t)m * HH + k4) = packed;   // persist fp16 enc
            }
        }

        // ---- prefetch next B, wait for current B only ----
        if (c + 1 < NCH) {
            issue_B(c + 1, nxtB);
            CP_COMMIT();
            CP_WAIT1();
        } else {
            CP_WAIT0();
        }
        __syncthreads();

        // ---- compute chunk c: 4 ksteps of 16 ----
        #pragma unroll
        for (int ks = 0; ks < 4; ks++) {
            const int k0 = ks * 16;
            uint32_t ah[2][4];
            #pragma unroll
            for (int mt = 0; mt < 2; mt++) {
                uint32_t ra = (wm + mt * 16 + a_r) * RSTRIDE + (k0 + a_k) * 2;
                ldm_x4(ah[mt], sb + SM_A + ra);
            }
            #pragma unroll
            for (int ntp = 0; ntp < 4; ntp++) {
                uint32_t rb = (wn + ntp * 16 + b_n) * RSTRIDE + (k0 + b_k) * 2;
                uint32_t bh[4];
                ldm_x4(bh, curB + rb);
                #pragma unroll
                for (int mt = 0; mt < 2; mt++)
                    #pragma unroll
                    for (int h = 0; h < 2; h++)
                        mma16816h(acc[mt][ntp * 2 + h], ah[mt], &bh[h * 2]);
            }
        }
        __syncthreads();   // A buffer reused next iteration
    }

    // ---- fused epilogue: tanh(+bias)*We, reduce over 256 cols ----
    const int wnidx = wid >> 2;
    #pragma unroll
    for (int mt = 0; mt < 2; mt++) {
        int r_lo = wm + mt * 16 + (lane >> 2);
        float s0 = 0.0f, s1 = 0.0f;
        #pragma unroll
        for (int nt = 0; nt < 8; nt++) {
            int col = wn + nt * 8 + (lane & 3) * 2;
            float w0 = swe[col], w1 = swe[col + 1];
            float bb0 = sbias[col], bb1 = sbias[col + 1];
            s0 = fmaf(fast_tanh(acc[mt][nt][0] + bb0), w0, s0);
            s0 = fmaf(fast_tanh(acc[mt][nt][1] + bb1), w1, s0);
            s1 = fmaf(fast_tanh(acc[mt][nt][2] + bb0), w0, s1);
            s1 = fmaf(fast_tanh(acc[mt][nt][3] + bb1), w1, s1);
        }
        s0 += __shfl_xor_sync(0xffffffffu, s0, 1);
        s0 += __shfl_xor_sync(0xffffffffu, s0, 2);
        s1 += __shfl_xor_sync(0xffffffffu, s1, 1);
        s1 += __shfl_xor_sync(0xffffffffu, s1, 2);
        if ((lane & 3) == 0) {
            red[r_lo * 4 + wnidx]       = s0;
            red[(r_lo + 8) * 4 + wnidx] = s1;
        }
    }
    __syncthreads();
    if (tid < TM) {
        const float* rp = red + tid * 4;
        g_scores[row0 + tid] = rp[0] + rp[1] + rp[2] + rp[3];  // b_e omitted
    }
}

// ---------------------------------------------------------------------------
// k2: softmax over S per batch. grid(B), block(1024). Writes attn to d_out.
// ---------------------------------------------------------------------------
__global__ __launch_bounds__(1024) void softmax_kernel(float* __restrict__ attn_out) {
    __shared__ float sv[SS];
    __shared__ float red[32];
    int b = blockIdx.x, t = threadIdx.x;
    int warp = t >> 5, lane = t & 31;

    float m = -1e30f;
    #pragma unroll
    for (int i = t; i < SS; i += 1024) {
        float v = g_scores[b * SS + i];
        sv[i] = v;
        m = fmaxf(m, v);
    }
    #pragma unroll
    for (int off = 16; off > 0; off >>= 1)
        m = fmaxf(m, __shfl_down_sync(0xffffffffu, m, off));
    if (lane == 0) red[warp] = m;
    __syncthreads();
    if (t == 0) {
        float mm = red[0];
        #pragma unroll
        for (int w = 1; w < 32; w++) mm = fmaxf(mm, red[w]);
        red[0] = mm;
    }
    __syncthreads();
    m = red[0];
    __syncthreads();

    float sum = 0.0f;
    #pragma unroll
    for (int i = t; i < SS; i += 1024) {
        float e = __expf(sv[i] - m);
        sv[i] = e;
        sum += e;
    }
    #pragma unroll
    for (int off = 16; off > 0; off >>= 1)
        sum += __shfl_down_sync(0xffffffffu, sum, off);
    if (lane == 0) red[warp] = sum;
    __syncthreads();
    if (t == 0) {
        float ss = 0.0f;
        #pragma unroll
        for (int w = 0; w < 32; w++) ss += red[w];
        red[0] = 1.0f / ss;
    }
    __syncthreads();
    float inv = red[0];
    #pragma unroll
    for (int i = t; i < SS; i += 1024)
        attn_out[b * SS + i] = sv[i] * inv;
}

// ---------------------------------------------------------------------------
// k3: context partials from fp16 enc copy (half the DRAM traffic).
// grid(32, B), block(128). Thread t owns h = 4t..4t+3 (8B loads).
// ---------------------------------------------------------------------------
__global__ void context_partial_kernel(const float* __restrict__ attn) {
    __shared__ float sa[128];
    int b  = blockIdx.y;
    int s0 = blockIdx.x * 128;
    int t  = threadIdx.x;           // 0..127
    sa[t] = attn[b * SS + s0 + t];
    __syncthreads();
    const __half* base = g_encH + ((size_t)b * SS + s0) * HH + t * 4;
    float4 acc = make_float4(0.f, 0.f, 0.f, 0.f);
    #pragma unroll 8
    for (int s = 0; s < 128; s++) {
        uint2 u = *(const uint2*)(base + (size_t)s * HH);
        __half2 p01 = *(__half2*)&u.x;
        __half2 p23 = *(__half2*)&u.y;
        float2 f01 = __half22float2(p01);
        float2 f23 = __half22float2(p23);
        float w = sa[s];
        acc.x = fmaf(w, f01.x, acc.x);
        acc.y = fmaf(w, f01.y, acc.y);
        acc.z = fmaf(w, f23.x, acc.z);
        acc.w = fmaf(w, f23.y, acc.w);
    }
    *(float4*)&g_ctx_part[(b * 32 + blockIdx.x) * HH + t * 4] = acc;
}

__global__ void context_reduce_kernel(float* __restrict__ ctx_out) {
    int b = blockIdx.x, h = threadIdx.x;
    float acc = 0.0f;
    #pragma unroll
    for (int sc = 0; sc < 32; sc++)
        acc += g_ctx_part[(b * 32 + sc) * HH + h];
    ctx_out[b * HH + h] = acc;
}

// ---------------------------------------------------------------------------
// entry point
// ---------------------------------------------------------------------------
extern "C" void kernel_launch(void* const* d_in, const int* in_sizes, int n_in,
                              void* d_out, int out_size) {
    const float* enc  = (const float*)d_in[0];
    const float* dh   = (const float*)d_in[1];
    const float* Wenc = (const float*)d_in[2];
    const float* benc = (const float*)d_in[3];
    const float* Wdec = (const float*)d_in[4];
    const float* bdec = (const float*)d_in[5];
    const float* We   = (const float*)d_in[6];

    float* ctx_out  = (float*)d_out;             // [B, H]
    float* attn_out = (float*)d_out + BB * HH;   // [B, S]

    cudaFuncSetAttribute(scores_mma_kernel,
                         cudaFuncAttributeMaxDynamicSharedMemorySize, SM_TOT);

    prep_B_kernel<<<HH, AA>>>(Wenc);
    dec_proj_kernel<<<BB, 256>>>(dh, Wdec, bdec);
    scores_mma_kernel<<<(BB * SS) / TM, 512, SM_TOT>>>(enc, benc, We);
    softmax_kernel<<<BB, 1024>>>(attn_out);
    context_partial_kernel<<<dim3(32, BB), 128>>>(attn_out);
    context_reduce_kernel<<<BB, HH>>>(ctx_out);
}

// round 13
// speedup vs baseline: 1.9070x; 1.1134x over previous
#include <cuda_runtime.h>
#include <cuda_fp16.h>
#include <cstdint>

// Problem shape (fixed)
#define BB 32
#define SS 4096
#define HH 512
#define AA 256

#define TM 128              // rows per CTA
#define KC 64               // K per chunk
#define NCH (HH / KC)       // 8 chunks

// ---------------- scratch (no allocs allowed) ----------------
__device__ float g_scores[BB * SS];
__device__ float g_decp[BB * AA];
__device__ float g_ctx_part[BB * 32 * HH];
// W_enc^T as fp16, [n=256][k=512] row-major (k contiguous)
__device__ __half g_Bh[AA * HH];
// fp16 copy of encoder_outputs, written by scores kernel
__device__ __half g_encH[(size_t)BB * SS * HH];   // 134 MB

// ---------------- helpers ----------------
__device__ __forceinline__ uint32_t smem_u32(const void* p) {
    uint32_t a;
    asm("{ .reg .u64 t; cvta.to.shared.u64 t, %1; cvt.u32.u64 %0, t; }"
        : "=r"(a) : "l"(p));
    return a;
}

__device__ __forceinline__ float fast_tanh(float x) {
    x = fminf(15.0f, fmaxf(-15.0f, x));
    float t = __expf(2.0f * x);
    return __fdividef(t - 1.0f, t + 1.0f);
}

__device__ __forceinline__ void ldm_x4(uint32_t* r, uint32_t addr) {
    asm volatile("ldmatrix.sync.aligned.m8n8.x4.shared.b16 {%0,%1,%2,%3}, [%4];"
                 : "=r"(r[0]), "=r"(r[1]), "=r"(r[2]), "=r"(r[3]) : "r"(addr));
}

__device__ __forceinline__ void mma16816h(float* d, const uint32_t* a, const uint32_t* b) {
    asm volatile(
        "mma.sync.aligned.m16n8k16.row.col.f32.f16.f16.f32 "
        "{%0,%1,%2,%3}, {%4,%5,%6,%7}, {%8,%9}, {%0,%1,%2,%3};"
        : "+f"(d[0]), "+f"(d[1]), "+f"(d[2]), "+f"(d[3])
        : "r"(a[0]), "r"(a[1]), "r"(a[2]), "r"(a[3]), "r"(b[0]), "r"(b[1]));
}

#define CP16(dst, src) \
    asm volatile("cp.async.ca.shared.global [%0], [%1], 16;" :: "r"(dst), "l"(src) : "memory")
#define CP_COMMIT() asm volatile("cp.async.commit_group;" ::: "memory")
#define CP_WAIT0()  asm volatile("cp.async.wait_group 0;"  ::: "memory")

// ---------------------------------------------------------------------------
// prep: W_enc[k][n] -> g_Bh[n][k] fp16, coalesced via 32x32 smem transpose.
// grid(HH/32, AA/32) = (16, 8), block(32, 8).
// ---------------------------------------------------------------------------
__global__ void prep_B_kernel(const float* __restrict__ Wenc) {
    __shared__ float tile[32][33];
    int kb = blockIdx.x * 32;       // k base
    int nb = blockIdx.y * 32;       // n base
    int tx = threadIdx.x, ty = threadIdx.y;
    #pragma unroll
    for (int r = 0; r < 4; r++)     // coalesced read along n
        tile[ty + r * 8][tx] = Wenc[(kb + ty + r * 8) * AA + nb + tx];
    __syncthreads();
    #pragma unroll
    for (int r = 0; r < 4; r++)     // coalesced write along k
        g_Bh[(nb + ty + r * 8) * HH + kb + tx] = __float2half(tile[tx][ty + r * 8]);
}

// ---------------------------------------------------------------------------
// k0: dec_p[b][a] = decoder_hidden[b] . W_dec[:,a] + b_dec[a]
// ---------------------------------------------------------------------------
__global__ void dec_proj_kernel(const float* __restrict__ dh,
                                const float* __restrict__ Wdec,
                                const float* __restrict__ bdec) {
    __shared__ float sdh[HH];
    int b = blockIdx.x, t = threadIdx.x;
    for (int k = t; k < HH; k += 256) sdh[k] = dh[b * HH + k];
    __syncthreads();
    float acc = bdec[t];
    #pragma unroll 8
    for (int k = 0; k < HH; k++) acc = fmaf(sdh[k], Wdec[k * AA + t], acc);
    g_decp[b * AA + t] = acc;
}

// ---------------------------------------------------------------------------
// k1: scores via mma.sync pure fp16, with A prefetched into registers during
// compute (B via cp.async double-buffer). A single-buffered in smem (96 KB
// total -> 2 CTAs/SM). Also persists A's fp16 conversion to g_encH.
// grid(1024), block(512). CTA tile 128x256, warp 4(M)x4(N).
// ---------------------------------------------------------------------------
#define RSTRIDE 144
#define ABUF    (128u * RSTRIDE)            // 18432 (fp16 A)
#define BBUF    (256u * RSTRIDE)            // 36864 (fp16 B)
#define SM_A    0u
#define SM_B0   ABUF                        // 18432
#define SM_B1   (SM_B0 + BBUF)              // 55296
#define SM_BIAS (SM_B1 + BBUF)              // 92160
#define SM_WE   (SM_BIAS + 1024u)
#define SM_RED  (SM_WE + 1024u)
#define SM_TOT  (SM_RED + 2048u)            // 96256 bytes

__global__ __launch_bounds__(512) void scores_mma_kernel(
    const float* __restrict__ enc,
    const float* __restrict__ benc,
    const float* __restrict__ We) {

    extern __shared__ char smem[];
    const uint32_t sb = smem_u32(smem);
    const int tid  = threadIdx.x;
    const int wid  = tid >> 5;
    const int lane = tid & 31;
    const int wm = (wid & 3) * 32;
    const int wn = (wid >> 2) * 64;
    const int row0 = blockIdx.x * TM;       // 128 | 4096 -> never crosses batch
    const int batch = row0 / SS;

    float* sbias = (float*)(smem + SM_BIAS);
    float* swe   = (float*)(smem + SM_WE);
    float* red   = (float*)(smem + SM_RED);
    if (tid < AA) {
        sbias[tid] = benc[tid] + g_decp[batch * AA + tid];
        swe[tid]   = We[tid];
    }

    float acc[2][8][4];
    #pragma unroll
    for (int mt = 0; mt < 2; mt++)
        #pragma unroll
        for (int nt = 0; nt < 8; nt++)
            #pragma unroll
            for (int q = 0; q < 4; q++) acc[mt][nt][q] = 0.0f;

    // ldmatrix lane addressing
    const int a_r = (lane & 7) + ((lane >> 3) & 1) * 8;
    const int a_k = (lane >> 4) * 8;
    const int b_n = (lane & 7) + (lane >> 4) * 8;
    const int b_k = ((lane >> 3) & 1) * 8;

    // per-thread A indices (fixed across chunks)
    const int am  = tid >> 4;               // row 0..31 (x4 via i)
    const int ak4 = (tid & 15) * 4;         // k offset of float4

    auto issue_B = [&](int c, uint32_t bbase) {
        const char* bh = (const char*)g_Bh;
        #pragma unroll
        for (int i = 0; i < 4; i++) {
            int idx = tid + i * 512;            // 0..2047
            int n   = idx >> 3;
            int ch  = idx & 7;
            size_t src = (size_t)(n * HH + c * KC + ch * 8) * 2;
            uint32_t dst = n * RSTRIDE + ch * 16;
            CP16(bbase + dst, bh + src);
        }
    };
    auto load_A = [&](int c, float4* v) {
        const float* Ab = enc + (size_t)row0 * HH + c * KC;
        #pragma unroll
        for (int i = 0; i < 4; i++)
            v[i] = *(const float4*)(Ab + (size_t)(am + i * 32) * HH + ak4);
    };
    auto store_A = [&](int c, const float4* v) {   // smem + g_encH from regs
        __half* Eh = g_encH + (size_t)row0 * HH + c * KC;
        #pragma unroll
        for (int i = 0; i < 4; i++) {
            int m = am + i * 32;
            float4 w = v[i];
            __half2 h01 = __floats2half2_rn(w.x, w.y);
            __half2 h23 = __floats2half2_rn(w.z, w.w);
            uint2 packed = make_uint2(*(uint32_t*)&h01, *(uint32_t*)&h23);
            *(uint2*)(smem + SM_A + m * RSTRIDE + ak4 * 2) = packed;
            *(uint2*)(Eh + (size_t)m * HH + ak4) = packed;
        }
    };

    // ---- prologue: chunk 0 (B async + A serial) ----
    float4 av[4];
    issue_B(0, sb + SM_B0);
    CP_COMMIT();
    load_A(0, av);
    store_A(0, av);
    CP_WAIT0();
    __syncthreads();

    for (int c = 0; c < NCH; c++) {
        const uint32_t curB = sb + ((c & 1) ? SM_B1 : SM_B0);
        const uint32_t nxtB = sb + ((c & 1) ? SM_B0 : SM_B1);

        // prefetch next chunk: B via cp.async, A into registers (LDGs fly
        // during the MMA section below)
        if (c + 1 < NCH) {
            issue_B(c + 1, nxtB);
            CP_COMMIT();
            load_A(c + 1, av);
        }

        // ---- compute chunk c: 4 ksteps of 16 ----
        #pragma unroll
        for (int ks = 0; ks < 4; ks++) {
            const int k0 = ks * 16;
            uint32_t ah[2][4];
            #pragma unroll
            for (int mt = 0; mt < 2; mt++) {
                uint32_t ra = (wm + mt * 16 + a_r) * RSTRIDE + (k0 + a_k) * 2;
                ldm_x4(ah[mt], sb + SM_A + ra);
            }
            #pragma unroll
            for (int ntp = 0; ntp < 4; ntp++) {
                uint32_t rb = (wn + ntp * 16 + b_n) * RSTRIDE + (k0 + b_k) * 2;
                uint32_t bh[4];
                ldm_x4(bh, curB + rb);
                #pragma unroll
                for (int mt = 0; mt < 2; mt++)
                    #pragma unroll
                    for (int h = 0; h < 2; h++)
                        mma16816h(acc[mt][ntp * 2 + h], ah[mt], &bh[h * 2]);
            }
        }
        __syncthreads();                    // all warps done reading smem A

        if (c + 1 < NCH) {
            store_A(c + 1, av);             // overwrite A buffer from regs
            CP_WAIT0();                     // B(c+1) landed during compute
        }
        __syncthreads();                    // A stores visible to all warps
    }

    // ---- fused epilogue: tanh(+bias)*We, reduce over 256 cols ----
    const int wnidx = wid >> 2;
    #pragma unroll
    for (int mt = 0; mt < 2; mt++) {
        int r_lo = wm + mt * 16 + (lane >> 2);
        float s0 = 0.0f, s1 = 0.0f;
        #pragma unroll
        for (int nt = 0; nt < 8; nt++) {
            int col = wn + nt * 8 + (lane & 3) * 2;
            float w0 = swe[col], w1 = swe[col + 1];
            float bb0 = sbias[col], bb1 = sbias[col + 1];
            s0 = fmaf(fast_tanh(acc[mt][nt][0] + bb0), w0, s0);
            s0 = fmaf(fast_tanh(acc[mt][nt][1] + bb1), w1, s0);
            s1 = fmaf(fast_tanh(acc[mt][nt][2] + bb0), w0, s1);
            s1 = fmaf(fast_tanh(acc[mt][nt][3] + bb1), w1, s1);
        }
        s0 += __shfl_xor_sync(0xffffffffu, s0, 1);
        s0 += __shfl_xor_sync(0xffffffffu, s0, 2);
        s1 += __shfl_xor_sync(0xffffffffu, s1, 1);
        s1 += __shfl_xor_sync(0xffffffffu, s1, 2);
        if ((lane & 3) == 0) {
            red[r_lo * 4 + wnidx]       = s0;
            red[(r_lo + 8) * 4 + wnidx] = s1;
        }
    }
    __syncthreads();
    if (tid < TM) {
        const float* rp = red + tid * 4;
        g_scores[row0 + tid] = rp[0] + rp[1] + rp[2] + rp[3];  // b_e omitted
    }
}

// ---------------------------------------------------------------------------
// k2: softmax over S per batch. grid(B), block(1024). Writes attn to d_out.
// ---------------------------------------------------------------------------
__global__ __launch_bounds__(1024) void softmax_kernel(float* __restrict__ attn_out) {
    __shared__ float sv[SS];
    __shared__ float red[32];
    int b = blockIdx.x, t = threadIdx.x;
    int warp = t >> 5, lane = t & 31;

    float m = -1e30f;
    #pragma unroll
    for (int i = t; i < SS; i += 1024) {
        float v = g_scores[b * SS + i];
        sv[i] = v;
        m = fmaxf(m, v);
    }
    #pragma unroll
    for (int off = 16; off > 0; off >>= 1)
        m = fmaxf(m, __shfl_down_sync(0xffffffffu, m, off));
    if (lane == 0) red[warp] = m;
    __syncthreads();
    if (t == 0) {
        float mm = red[0];
        #pragma unroll
        for (int w = 1; w < 32; w++) mm = fmaxf(mm, red[w]);
        red[0] = mm;
    }
    __syncthreads();
    m = red[0];
    __syncthreads();

    float sum = 0.0f;
    #pragma unroll
    for (int i = t; i < SS; i += 1024) {
        float e = __expf(sv[i] - m);
        sv[i] = e;
        sum += e;
    }
    #pragma unroll
    for (int off = 16; off > 0; off >>= 1)
        sum += __shfl_down_sync(0xffffffffu, sum, off);
    if (lane == 0) red[warp] = sum;
    __syncthreads();
    if (t == 0) {
        float ss = 0.0f;
        #pragma unroll
        for (int w = 0; w < 32; w++) ss += red[w];
        red[0] = 1.0f / ss;
    }
    __syncthreads();
    float inv = red[0];
    #pragma unroll
    for (int i = t; i < SS; i += 1024)
        attn_out[b * SS + i] = sv[i] * inv;
}

// ---------------------------------------------------------------------------
// k3: context partials from fp16 enc copy. grid(32, B), block(128).
// ---------------------------------------------------------------------------
__global__ void context_partial_kernel(const float* __restrict__ attn) {
    __shared__ float sa[128];
    int b  = blockIdx.y;
    int s0 = blockIdx.x * 128;
    int t  = threadIdx.x;           // 0..127
    sa[t] = attn[b * SS + s0 + t];
    __syncthreads();
    const __half* base = g_encH + ((size_t)b * SS + s0) * HH + t * 4;
    float4 acc = make_float4(0.f, 0.f, 0.f, 0.f);
    #pragma unroll 8
    for (int s = 0; s < 128; s++) {
        uint2 u = *(const uint2*)(base + (size_t)s * HH);
        __half2 p01 = *(__half2*)&u.x;
        __half2 p23 = *(__half2*)&u.y;
        float2 f01 = __half22float2(p01);
        float2 f23 = __half22float2(p23);
        float w = sa[s];
        acc.x = fmaf(w, f01.x, acc.x);
        acc.y = fmaf(w, f01.y, acc.y);
        acc.z = fmaf(w, f23.x, acc.z);
        acc.w = fmaf(w, f23.y, acc.w);
    }
    *(float4*)&g_ctx_part[(b * 32 + blockIdx.x) * HH + t * 4] = acc;
}

__global__ void context_reduce_kernel(float* __restrict__ ctx_out) {
    int b = blockIdx.x, h = threadIdx.x;
    float acc = 0.0f;
    #pragma unroll
    for (int sc = 0; sc < 32; sc++)
        acc += g_ctx_part[(b * 32 + sc) * HH + h];
    ctx_out[b * HH + h] = acc;
}

// ---------------------------------------------------------------------------
// entry point
// ---------------------------------------------------------------------------
extern "C" void kernel_launch(void* const* d_in, const int* in_sizes, int n_in,
                              void* d_out, int out_size) {
    const float* enc  = (const float*)d_in[0];
    const float* dh   = (const float*)d_in[1];
    const float* Wenc = (const float*)d_in[2];
    const float* benc = (const float*)d_in[3];
    const float* Wdec = (const float*)d_in[4];
    const float* bdec = (const float*)d_in[5];
    const float* We   = (const float*)d_in[6];

    float* ctx_out  = (float*)d_out;             // [B, H]
    float* attn_out = (float*)d_out + BB * HH;   // [B, S]

    cudaFuncSetAttribute(scores_mma_kernel,
                         cudaFuncAttributeMaxDynamicSharedMemorySize, SM_TOT);

    prep_B_kernel<<<dim3(HH / 32, AA / 32), dim3(32, 8)>>>(Wenc);
    dec_proj_kernel<<<BB, 256>>>(dh, Wdec, bdec);
    scores_mma_kernel<<<(BB * SS) / TM, 512, SM_TOT>>>(enc, benc, We);
    softmax_kernel<<<BB, 1024>>>(attn_out);
    context_partial_kernel<<<dim3(32, BB), 128>>>(attn_out);
    context_reduce_kernel<<<BB, HH>>>(ctx_out);
}

// round 14
// speedup vs baseline: 2.0272x; 1.0630x over previous
#include <cuda_runtime.h>
#include <cuda_fp16.h>
#include <cstdint>

// Problem shape (fixed)
#define BB 32
#define SS 4096
#define HH 512
#define AA 256

#define TM 128              // rows per CTA
#define KC 64               // K per chunk
#define NCH (HH / KC)       // 8 chunks

// ---------------- scratch (no allocs allowed) ----------------
__device__ float g_scores[BB * SS];
__device__ float g_decp[BB * AA];
__device__ float g_ctx_part[BB * 32 * HH];
// W_enc^T as fp16, [n=256][k=512] row-major (k contiguous)
__device__ __half g_Bh[AA * HH];
// fp16 copy of encoder_outputs, written by scores kernel
__device__ __half g_encH[(size_t)BB * SS * HH];   // 134 MB

// ---------------- helpers ----------------
__device__ __forceinline__ uint32_t smem_u32(const void* p) {
    uint32_t a;
    asm("{ .reg .u64 t; cvta.to.shared.u64 t, %1; cvt.u32.u64 %0, t; }"
        : "=r"(a) : "l"(p));
    return a;
}

// single-MUFU tanh (sm_75+): abs err ~2^-10.7, saturating
__device__ __forceinline__ float fast_tanh(float x) {
    float y;
    asm("tanh.approx.f32 %0, %1;" : "=f"(y) : "f"(x));
    return y;
}

__device__ __forceinline__ void ldm_x4(uint32_t* r, uint32_t addr) {
    asm volatile("ldmatrix.sync.aligned.m8n8.x4.shared.b16 {%0,%1,%2,%3}, [%4];"
                 : "=r"(r[0]), "=r"(r[1]), "=r"(r[2]), "=r"(r[3]) : "r"(addr));
}

__device__ __forceinline__ void mma16816h(float* d, const uint32_t* a, const uint32_t* b) {
    asm volatile(
        "mma.sync.aligned.m16n8k16.row.col.f32.f16.f16.f32 "
        "{%0,%1,%2,%3}, {%4,%5,%6,%7}, {%8,%9}, {%0,%1,%2,%3};"
        : "+f"(d[0]), "+f"(d[1]), "+f"(d[2]), "+f"(d[3])
        : "r"(a[0]), "r"(a[1]), "r"(a[2]), "r"(a[3]), "r"(b[0]), "r"(b[1]));
}

#define CP16(dst, src) \
    asm volatile("cp.async.ca.shared.global [%0], [%1], 16;" :: "r"(dst), "l"(src) : "memory")
#define CP_COMMIT() asm volatile("cp.async.commit_group;" ::: "memory")
#define CP_WAIT0()  asm volatile("cp.async.wait_group 0;"  ::: "memory")

// ---------------------------------------------------------------------------
// fused prep: blocks 0..127 transpose W_enc -> g_Bh fp16 (32x32 smem tiles);
// blocks 128..159 compute dec_p. block(256).
// ---------------------------------------------------------------------------
__global__ void prep_fused_kernel(const float* __restrict__ Wenc,
                                  const float* __restrict__ dh,
                                  const float* __restrict__ Wdec,
                                  const float* __restrict__ bdec) {
    if (blockIdx.x < 128) {
        __shared__ float tile[32][33];
        int kb = (blockIdx.x & 15) * 32;    // k base (16 tiles)
        int nb = (blockIdx.x >> 4) * 32;    // n base (8 tiles)
        int tx = threadIdx.x & 31, ty = threadIdx.x >> 5;   // 32 x 8
        #pragma unroll
        for (int r = 0; r < 4; r++)         // coalesced read along n
            tile[ty + r * 8][tx] = Wenc[(kb + ty + r * 8) * AA + nb + tx];
        __syncthreads();
        #pragma unroll
        for (int r = 0; r < 4; r++)         // coalesced write along k
            g_Bh[(nb + ty + r * 8) * HH + kb + tx] = __float2half(tile[tx][ty + r * 8]);
    } else {
        __shared__ float sdh[HH];
        int b = blockIdx.x - 128;
        int t = threadIdx.x;
        for (int k = t; k < HH; k += 256) sdh[k] = dh[b * HH + k];
        __syncthreads();
        float acc = bdec[t];
        #pragma unroll 8
        for (int k = 0; k < HH; k++) acc = fmaf(sdh[k], Wdec[k * AA + t], acc);
        g_decp[b * AA + t] = acc;
    }
}

// ---------------------------------------------------------------------------
// k1: scores via mma.sync pure fp16, A register-prefetch + B cp.async
// double-buffer. Persists fp16 enc to g_encH. grid(1024), block(512).
// ---------------------------------------------------------------------------
#define RSTRIDE 144
#define ABUF    (128u * RSTRIDE)            // 18432 (fp16 A)
#define BBUF    (256u * RSTRIDE)            // 36864 (fp16 B)
#define SM_A    0u
#define SM_B0   ABUF                        // 18432
#define SM_B1   (SM_B0 + BBUF)              // 55296
#define SM_BIAS (SM_B1 + BBUF)              // 92160
#define SM_WE   (SM_BIAS + 1024u)
#define SM_RED  (SM_WE + 1024u)
#define SM_TOT  (SM_RED + 2048u)            // 96256 bytes

__global__ __launch_bounds__(512) void scores_mma_kernel(
    const float* __restrict__ enc,
    const float* __restrict__ benc,
    const float* __restrict__ We) {

    extern __shared__ char smem[];
    const uint32_t sb = smem_u32(smem);
    const int tid  = threadIdx.x;
    const int wid  = tid >> 5;
    const int lane = tid & 31;
    const int wm = (wid & 3) * 32;
    const int wn = (wid >> 2) * 64;
    const int row0 = blockIdx.x * TM;       // 128 | 4096 -> never crosses batch
    const int batch = row0 / SS;

    float* sbias = (float*)(smem + SM_BIAS);
    float* swe   = (float*)(smem + SM_WE);
    float* red   = (float*)(smem + SM_RED);
    if (tid < AA) {
        sbias[tid] = benc[tid] + g_decp[batch * AA + tid];
        swe[tid]   = We[tid];
    }

    float acc[2][8][4];
    #pragma unroll
    for (int mt = 0; mt < 2; mt++)
        #pragma unroll
        for (int nt = 0; nt < 8; nt++)
            #pragma unroll
            for (int q = 0; q < 4; q++) acc[mt][nt][q] = 0.0f;

    // ldmatrix lane addressing
    const int a_r = (lane & 7) + ((lane >> 3) & 1) * 8;
    const int a_k = (lane >> 4) * 8;
    const int b_n = (lane & 7) + (lane >> 4) * 8;
    const int b_k = ((lane >> 3) & 1) * 8;

    // per-thread A indices (fixed across chunks)
    const int am  = tid >> 4;               // row 0..31 (x4 via i)
    const int ak4 = (tid & 15) * 4;         // k offset of float4

    auto issue_B = [&](int c, uint32_t bbase) {
        const char* bh = (const char*)g_Bh;
        #pragma unroll
        for (int i = 0; i < 4; i++) {
            int idx = tid + i * 512;            // 0..2047
            int n   = idx >> 3;
            int ch  = idx & 7;
            size_t src = (size_t)(n * HH + c * KC + ch * 8) * 2;
            uint32_t dst = n * RSTRIDE + ch * 16;
            CP16(bbase + dst, bh + src);
        }
    };
    auto load_A = [&](int c, float4* v) {
        const float* Ab = enc + (size_t)row0 * HH + c * KC;
        #pragma unroll
        for (int i = 0; i < 4; i++)
            v[i] = *(const float4*)(Ab + (size_t)(am + i * 32) * HH + ak4);
    };
    auto store_A = [&](int c, const float4* v) {   // smem + g_encH from regs
        __half* Eh = g_encH + (size_t)row0 * HH + c * KC;
        #pragma unroll
        for (int i = 0; i < 4; i++) {
            int m = am + i * 32;
            float4 w = v[i];
            __half2 h01 = __floats2half2_rn(w.x, w.y);
            __half2 h23 = __floats2half2_rn(w.z, w.w);
            uint2 packed = make_uint2(*(uint32_t*)&h01, *(uint32_t*)&h23);
            *(uint2*)(smem + SM_A + m * RSTRIDE + ak4 * 2) = packed;
            *(uint2*)(Eh + (size_t)m * HH + ak4) = packed;
        }
    };

    // ---- prologue: chunk 0 (B async + A serial) ----
    float4 av[4];
    issue_B(0, sb + SM_B0);
    CP_COMMIT();
    load_A(0, av);
    store_A(0, av);
    CP_WAIT0();
    __syncthreads();

    for (int c = 0; c < NCH; c++) {
        const uint32_t curB = sb + ((c & 1) ? SM_B1 : SM_B0);
        const uint32_t nxtB = sb + ((c & 1) ? SM_B0 : SM_B1);

        if (c + 1 < NCH) {
            issue_B(c + 1, nxtB);
            CP_COMMIT();
            load_A(c + 1, av);      // LDGs fly during MMA section
        }

        // ---- compute chunk c: 4 ksteps of 16 ----
        #pragma unroll
        for (int ks = 0; ks < 4; ks++) {
            const int k0 = ks * 16;
            uint32_t ah[2][4];
            #pragma unroll
            for (int mt = 0; mt < 2; mt++) {
                uint32_t ra = (wm + mt * 16 + a_r) * RSTRIDE + (k0 + a_k) * 2;
                ldm_x4(ah[mt], sb + SM_A + ra);
            }
            #pragma unroll
            for (int ntp = 0; ntp < 4; ntp++) {
                uint32_t rb = (wn + ntp * 16 + b_n) * RSTRIDE + (k0 + b_k) * 2;
                uint32_t bh[4];
                ldm_x4(bh, curB + rb);
                #pragma unroll
                for (int mt = 0; mt < 2; mt++)
                    #pragma unroll
                    for (int h = 0; h < 2; h++)
                        mma16816h(acc[mt][ntp * 2 + h], ah[mt], &bh[h * 2]);
            }
        }
        __syncthreads();                    // all warps done reading smem A

        if (c + 1 < NCH) {
            store_A(c + 1, av);             // overwrite A buffer from regs
            CP_WAIT0();                     // B(c+1) landed during compute
        }
        __syncthreads();                    // A stores visible to all warps
    }

    // ---- fused epilogue: tanh(+bias)*We, reduce over 256 cols ----
    const int wnidx = wid >> 2;
    #pragma unroll
    for (int mt = 0; mt < 2; mt++) {
        int r_lo = wm + mt * 16 + (lane >> 2);
        float s0 = 0.0f, s1 = 0.0f;
        #pragma unroll
        for (int nt = 0; nt < 8; nt++) {
            int col = wn + nt * 8 + (lane & 3) * 2;
            float w0 = swe[col], w1 = swe[col + 1];
            float bb0 = sbias[col], bb1 = sbias[col + 1];
            s0 = fmaf(fast_tanh(acc[mt][nt][0] + bb0), w0, s0);
            s0 = fmaf(fast_tanh(acc[mt][nt][1] + bb1), w1, s0);
            s1 = fmaf(fast_tanh(acc[mt][nt][2] + bb0), w0, s1);
            s1 = fmaf(fast_tanh(acc[mt][nt][3] + bb1), w1, s1);
        }
        s0 += __shfl_xor_sync(0xffffffffu, s0, 1);
        s0 += __shfl_xor_sync(0xffffffffu, s0, 2);
        s1 += __shfl_xor_sync(0xffffffffu, s1, 1);
        s1 += __shfl_xor_sync(0xffffffffu, s1, 2);
        if ((lane & 3) == 0) {
            red[r_lo * 4 + wnidx]       = s0;
            red[(r_lo + 8) * 4 + wnidx] = s1;
        }
    }
    __syncthreads();
    if (tid < TM) {
        const float* rp = red + tid * 4;
        g_scores[row0 + tid] = rp[0] + rp[1] + rp[2] + rp[3];  // b_e omitted
    }
}

// ---------------------------------------------------------------------------
// k2: softmax over S per batch. grid(B), block(1024). Writes attn to d_out.
// ---------------------------------------------------------------------------
__global__ __launch_bounds__(1024) void softmax_kernel(float* __restrict__ attn_out) {
    __shared__ float sv[SS];
    __shared__ float red[32];
    int b = blockIdx.x, t = threadIdx.x;
    int warp = t >> 5, lane = t & 31;

    float m = -1e30f;
    #pragma unroll
    for (int i = t; i < SS; i += 1024) {
        float v = g_scores[b * SS + i];
        sv[i] = v;
        m = fmaxf(m, v);
    }
    #pragma unroll
    for (int off = 16; off > 0; off >>= 1)
        m = fmaxf(m, __shfl_down_sync(0xffffffffu, m, off));
    if (lane == 0) red[warp] = m;
    __syncthreads();
    if (t == 0) {
        float mm = red[0];
        #pragma unroll
        for (int w = 1; w < 32; w++) mm = fmaxf(mm, red[w]);
        red[0] = mm;
    }
    __syncthreads();
    m = red[0];
    __syncthreads();

    float sum = 0.0f;
    #pragma unroll
    for (int i = t; i < SS; i += 1024) {
        float e = __expf(sv[i] - m);
        sv[i] = e;
        sum += e;
    }
    #pragma unroll
    for (int off = 16; off > 0; off >>= 1)
        sum += __shfl_down_sync(0xffffffffu, sum, off);
    if (lane == 0) red[warp] = sum;
    __syncthreads();
    if (t == 0) {
        float ss = 0.0f;
        #pragma unroll
        for (int w = 0; w < 32; w++) ss += red[w];
        red[0] = 1.0f / ss;
    }
    __syncthreads();
    float inv = red[0];
    #pragma unroll
    for (int i = t; i < SS; i += 1024)
        attn_out[b * SS + i] = sv[i] * inv;
}

// ---------------------------------------------------------------------------
// k3: context partials from fp16 enc copy. grid(32, B), block(128).
// ---------------------------------------------------------------------------
__global__ void context_partial_kernel(const float* __restrict__ attn) {
    __shared__ float sa[128];
    int b  = blockIdx.y;
    int s0 = blockIdx.x * 128;
    int t  = threadIdx.x;           // 0..127
    sa[t] = attn[b * SS + s0 + t];
    __syncthreads();
    const __half* base = g_encH + ((size_t)b * SS + s0) * HH + t * 4;
    float4 acc = make_float4(0.f, 0.f, 0.f, 0.f);
    #pragma unroll 8
    for (int s = 0; s < 128; s++) {
        uint2 u = *(const uint2*)(base + (size_t)s * HH);
        __half2 p01 = *(__half2*)&u.x;
        __half2 p23 = *(__half2*)&u.y;
        float2 f01 = __half22float2(p01);
        float2 f23 = __half22float2(p23);
        float w = sa[s];
        acc.x = fmaf(w, f01.x, acc.x);
        acc.y = fmaf(w, f01.y, acc.y);
        acc.z = fmaf(w, f23.x, acc.z);
        acc.w = fmaf(w, f23.y, acc.w);
    }
    *(float4*)&g_ctx_part[(b * 32 + blockIdx.x) * HH + t * 4] = acc;
}

__global__ void context_reduce_kernel(float* __restrict__ ctx_out) {
    int b = blockIdx.x, h = threadIdx.x;
    float acc = 0.0f;
    #pragma unroll
    for (int sc = 0; sc < 32; sc++)
        acc += g_ctx_part[(b * 32 + sc) * HH + h];
    ctx_out[b * HH + h] = acc;
}

// ---------------------------------------------------------------------------
// entry point
// ---------------------------------------------------------------------------
extern "C" void kernel_launch(void* const* d_in, const int* in_sizes, int n_in,
                              void* d_out, int out_size) {
    const float* enc  = (const float*)d_in[0];
    const float* dh   = (const float*)d_in[1];
    const float* Wenc = (const float*)d_in[2];
    const float* benc = (const float*)d_in[3];
    const float* Wdec = (const float*)d_in[4];
    const float* bdec = (const float*)d_in[5];
    const float* We   = (const float*)d_in[6];

    float* ctx_out  = (float*)d_out;             // [B, H]
    float* attn_out = (float*)d_out + BB * HH;   // [B, S]

    cudaFuncSetAttribute(scores_mma_kernel,
                         cudaFuncAttributeMaxDynamicSharedMemorySize, SM_TOT);

    prep_fused_kernel<<<160, 256>>>(Wenc, dh, Wdec, bdec);
    scores_mma_kernel<<<(BB * SS) / TM, 512, SM_TOT>>>(enc, benc, We);
    softmax_kernel<<<BB, 1024>>>(attn_out);
    context_partial_kernel<<<dim3(32, BB), 128>>>(attn_out);
    context_reduce_kernel<<<BB, HH>>>(ctx_out);
}

// round 15
// speedup vs baseline: 2.0935x; 1.0327x over previous
#include <cuda_runtime.h>
#include <cuda_fp16.h>
#include <cstdint>

// Problem shape (fixed)
#define BB 32
#define SS 4096
#define HH 512
#define AA 256

#define TM 128              // rows per CTA
#define KC 64               // K per chunk
#define NCH (HH / KC)       // 8 chunks

// ---------------- scratch (no allocs allowed) ----------------
__device__ float g_scores[BB * SS];
__device__ float g_decp[BB * AA];
__device__ float g_ctx_part[BB * 64 * HH];        // 64 s-chunks of partials
// W_enc^T as fp16, [n=256][k=512] row-major (k contiguous)
__device__ __half g_Bh[AA * HH];
// fp16 copy of encoder_outputs, written by scores kernel
__device__ __half g_encH[(size_t)BB * SS * HH];   // 134 MB

// ---------------- helpers ----------------
__device__ __forceinline__ uint32_t smem_u32(const void* p) {
    uint32_t a;
    asm("{ .reg .u64 t; cvta.to.shared.u64 t, %1; cvt.u32.u64 %0, t; }"
        : "=r"(a) : "l"(p));
    return a;
}

// single-MUFU tanh (sm_75+): abs err ~2^-10.7, saturating
__device__ __forceinline__ float fast_tanh(float x) {
    float y;
    asm("tanh.approx.f32 %0, %1;" : "=f"(y) : "f"(x));
    return y;
}

__device__ __forceinline__ void ldm_x4(uint32_t* r, uint32_t addr) {
    asm volatile("ldmatrix.sync.aligned.m8n8.x4.shared.b16 {%0,%1,%2,%3}, [%4];"
                 : "=r"(r[0]), "=r"(r[1]), "=r"(r[2]), "=r"(r[3]) : "r"(addr));
}

__device__ __forceinline__ void mma16816h(float* d, const uint32_t* a, const uint32_t* b) {
    asm volatile(
        "mma.sync.aligned.m16n8k16.row.col.f32.f16.f16.f32 "
        "{%0,%1,%2,%3}, {%4,%5,%6,%7}, {%8,%9}, {%0,%1,%2,%3};"
        : "+f"(d[0]), "+f"(d[1]), "+f"(d[2]), "+f"(d[3])
        : "r"(a[0]), "r"(a[1]), "r"(a[2]), "r"(a[3]), "r"(b[0]), "r"(b[1]));
}

#define CP16(dst, src) \
    asm volatile("cp.async.ca.shared.global [%0], [%1], 16;" :: "r"(dst), "l"(src) : "memory")
#define CP_COMMIT() asm volatile("cp.async.commit_group;" ::: "memory")
#define CP_WAIT0()  asm volatile("cp.async.wait_group 0;"  ::: "memory")

// ---------------------------------------------------------------------------
// fused prep: blocks 0..127 transpose W_enc -> g_Bh fp16 (32x32 smem tiles);
// blocks 128..159 compute dec_p. block(256).
// ---------------------------------------------------------------------------
__global__ void prep_fused_kernel(const float* __restrict__ Wenc,
                                  const float* __restrict__ dh,
                                  const float* __restrict__ Wdec,
                                  const float* __restrict__ bdec) {
    if (blockIdx.x < 128) {
        __shared__ float tile[32][33];
        int kb = (blockIdx.x & 15) * 32;    // k base (16 tiles)
        int nb = (blockIdx.x >> 4) * 32;    // n base (8 tiles)
        int tx = threadIdx.x & 31, ty = threadIdx.x >> 5;   // 32 x 8
        #pragma unroll
        for (int r = 0; r < 4; r++)         // coalesced read along n
            tile[ty + r * 8][tx] = Wenc[(kb + ty + r * 8) * AA + nb + tx];
        __syncthreads();
        #pragma unroll
        for (int r = 0; r < 4; r++)         // coalesced write along k
            g_Bh[(nb + ty + r * 8) * HH + kb + tx] = __float2half(tile[tx][ty + r * 8]);
    } else {
        __shared__ float sdh[HH];
        int b = blockIdx.x - 128;
        int t = threadIdx.x;
        for (int k = t; k < HH; k += 256) sdh[k] = dh[b * HH + k];
        __syncthreads();
        float acc = bdec[t];
        #pragma unroll 8
        for (int k = 0; k < HH; k++) acc = fmaf(sdh[k], Wdec[k * AA + t], acc);
        g_decp[b * AA + t] = acc;
    }
}

// ---------------------------------------------------------------------------
// k1: scores via mma.sync pure fp16. A register-prefetch + A smem double-
// buffer (one sync per chunk) + B cp.async double-buffer. Persists fp16 enc
// to g_encH. grid(1024), block(512). CTA tile 128x256, warp 4(M)x4(N).
// ---------------------------------------------------------------------------
#define RSTRIDE 144
#define ABUF    (128u * RSTRIDE)            // 18432 (fp16 A)
#define BBUF    (256u * RSTRIDE)            // 36864 (fp16 B)
#define SM_A0   0u
#define SM_A1   ABUF                        // 18432
#define SM_B0   (2u * ABUF)                 // 36864
#define SM_B1   (SM_B0 + BBUF)              // 73728
#define SM_BIAS (SM_B1 + BBUF)              // 110592
#define SM_WE   (SM_BIAS + 1024u)
#define SM_RED  (SM_WE + 1024u)
#define SM_TOT  (SM_RED + 2048u)            // 114688 bytes

__global__ __launch_bounds__(512) void scores_mma_kernel(
    const float* __restrict__ enc,
    const float* __restrict__ benc,
    const float* __restrict__ We) {

    extern __shared__ char smem[];
    const uint32_t sb = smem_u32(smem);
    const int tid  = threadIdx.x;
    const int wid  = tid >> 5;
    const int lane = tid & 31;
    const int wm = (wid & 3) * 32;
    const int wn = (wid >> 2) * 64;
    const int row0 = blockIdx.x * TM;       // 128 | 4096 -> never crosses batch
    const int batch = row0 / SS;

    float* sbias = (float*)(smem + SM_BIAS);
    float* swe   = (float*)(smem + SM_WE);
    float* red   = (float*)(smem + SM_RED);
    if (tid < AA) {
        sbias[tid] = benc[tid] + g_decp[batch * AA + tid];
        swe[tid]   = We[tid];
    }

    float acc[2][8][4];
    #pragma unroll
    for (int mt = 0; mt < 2; mt++)
        #pragma unroll
        for (int nt = 0; nt < 8; nt++)
            #pragma unroll
            for (int q = 0; q < 4; q++) acc[mt][nt][q] = 0.0f;

    // ldmatrix lane addressing
    const int a_r = (lane & 7) + ((lane >> 3) & 1) * 8;
    const int a_k = (lane >> 4) * 8;
    const int b_n = (lane & 7) + (lane >> 4) * 8;
    const int b_k = ((lane >> 3) & 1) * 8;

    // per-thread A indices (fixed across chunks)
    const int am  = tid >> 4;               // row 0..31 (x4 via i)
    const int ak4 = (tid & 15) * 4;         // k offset of float4

    auto issue_B = [&](int c, uint32_t bbase) {
        const char* bh = (const char*)g_Bh;
        #pragma unroll
        for (int i = 0; i < 4; i++) {
            int idx = tid + i * 512;            // 0..2047
            int n   = idx >> 3;
            int ch  = idx & 7;
            size_t src = (size_t)(n * HH + c * KC + ch * 8) * 2;
            uint32_t dst = n * RSTRIDE + ch * 16;
            CP16(bbase + dst, bh + src);
        }
    };
    auto load_A = [&](int c, float4* v) {
        const float* Ab = enc + (size_t)row0 * HH + c * KC;
        #pragma unroll
        for (int i = 0; i < 4; i++)
            v[i] = *(const float4*)(Ab + (size_t)(am + i * 32) * HH + ak4);
    };
    auto store_A = [&](int c, const float4* v, uint32_t abase) {
        __half* Eh = g_encH + (size_t)row0 * HH + c * KC;
        #pragma unroll
        for (int i = 0; i < 4; i++) {
            int m = am + i * 32;
            float4 w = v[i];
            __half2 h01 = __floats2half2_rn(w.x, w.y);
            __half2 h23 = __floats2half2_rn(w.z, w.w);
            uint2 packed = make_uint2(*(uint32_t*)&h01, *(uint32_t*)&h23);
            *(uint2*)(smem + abase + m * RSTRIDE + ak4 * 2) = packed;
            *(uint2*)(Eh + (size_t)m * HH + ak4) = packed;
        }
    };

    // ---- prologue: chunk 0 (B async + A serial, into buffer 0) ----
    float4 av[4];
    issue_B(0, sb + SM_B0);
    CP_COMMIT();
    load_A(0, av);
    store_A(0, av, SM_A0);
    CP_WAIT0();
    __syncthreads();

    for (int c = 0; c < NCH; c++) {
        const uint32_t curA = (c & 1) ? SM_A1 : SM_A0;
        const uint32_t nxtA = (c & 1) ? SM_A0 : SM_A1;
        const uint32_t curB = sb + ((c & 1) ? SM_B1 : SM_B0);
        const uint32_t nxtB = sb + ((c & 1) ? SM_B0 : SM_B1);

        if (c + 1 < NCH) {
            issue_B(c + 1, nxtB);
            CP_COMMIT();
            load_A(c + 1, av);      // LDGs fly during MMA section
        }

        // ---- compute chunk c: 4 ksteps of 16 ----
        #pragma unroll
        for (int ks = 0; ks < 4; ks++) {
            const int k0 = ks * 16;
            uint32_t ah[2][4];
            #pragma unroll
            for (int mt = 0; mt < 2; mt++) {
                uint32_t ra = (wm + mt * 16 + a_r) * RSTRIDE + (k0 + a_k) * 2;
                ldm_x4(ah[mt], sb + curA + ra);
            }
            #pragma unroll
            for (int ntp = 0; ntp < 4; ntp++) {
                uint32_t rb = (wn + ntp * 16 + b_n) * RSTRIDE + (k0 + b_k) * 2;
                uint32_t bh[4];
                ldm_x4(bh, curB + rb);
                #pragma unroll
                for (int mt = 0; mt < 2; mt++)
                    #pragma unroll
                    for (int h = 0; h < 2; h++)
                        mma16816h(acc[mt][ntp * 2 + h], ah[mt], &bh[h * 2]);
            }
        }

        // store next A into the idle buffer (no barrier needed before this —
        // writes don't touch curA/curB), then wait for next B, one sync.
        if (c + 1 < NCH) {
            store_A(c + 1, av, nxtA);
            CP_WAIT0();
        }
        __syncthreads();
    }

    // ---- fused epilogue: tanh(+bias)*We, reduce over 256 cols ----
    const int wnidx = wid >> 2;
    #pragma unroll
    for (int mt = 0; mt < 2; mt++) {
        int r_lo = wm + mt * 16 + (lane >> 2);
        float s0 = 0.0f, s1 = 0.0f;
        #pragma unroll
        for (int nt = 0; nt < 8; nt++) {
            int col = wn + nt * 8 + (lane & 3) * 2;
            float w0 = swe[col], w1 = swe[col + 1];
            float bb0 = sbias[col], bb1 = sbias[col + 1];
            s0 = fmaf(fast_tanh(acc[mt][nt][0] + bb0), w0, s0);
            s0 = fmaf(fast_tanh(acc[mt][nt][1] + bb1), w1, s0);
            s1 = fmaf(fast_tanh(acc[mt][nt][2] + bb0), w0, s1);
            s1 = fmaf(fast_tanh(acc[mt][nt][3] + bb1), w1, s1);
        }
        s0 += __shfl_xor_sync(0xffffffffu, s0, 1);
        s0 += __shfl_xor_sync(0xffffffffu, s0, 2);
        s1 += __shfl_xor_sync(0xffffffffu, s1, 1);
        s1 += __shfl_xor_sync(0xffffffffu, s1, 2);
        if ((lane & 3) == 0) {
            red[r_lo * 4 + wnidx]       = s0;
            red[(r_lo + 8) * 4 + wnidx] = s1;
        }
    }
    __syncthreads();
    if (tid < TM) {
        const float* rp = red + tid * 4;
        g_scores[row0 + tid] = rp[0] + rp[1] + rp[2] + rp[3];  // b_e omitted
    }
}

// ---------------------------------------------------------------------------
// k2: softmax over S per batch. grid(B), block(1024). Writes attn to d_out.
// ---------------------------------------------------------------------------
__global__ __launch_bounds__(1024) void softmax_kernel(float* __restrict__ attn_out) {
    __shared__ float sv[SS];
    __shared__ float red[32];
    int b = blockIdx.x, t = threadIdx.x;
    int warp = t >> 5, lane = t & 31;

    float m = -1e30f;
    #pragma unroll
    for (int i = t; i < SS; i += 1024) {
        float v = g_scores[b * SS + i];
        sv[i] = v;
        m = fmaxf(m, v);
    }
    #pragma unroll
    for (int off = 16; off > 0; off >>= 1)
        m = fmaxf(m, __shfl_down_sync(0xffffffffu, m, off));
    if (lane == 0) red[warp] = m;
    __syncthreads();
    if (t == 0) {
        float mm = red[0];
        #pragma unroll
        for (int w = 1; w < 32; w++) mm = fmaxf(mm, red[w]);
        red[0] = mm;
    }
    __syncthreads();
    m = red[0];
    __syncthreads();

    float sum = 0.0f;
    #pragma unroll
    for (int i = t; i < SS; i += 1024) {
        float e = __expf(sv[i] - m);
        sv[i] = e;
        sum += e;
    }
    #pragma unroll
    for (int off = 16; off > 0; off >>= 1)
        sum += __shfl_down_sync(0xffffffffu, sum, off);
    if (lane == 0) red[warp] = sum;
    __syncthreads();
    if (t == 0) {
        float ss = 0.0f;
        #pragma unroll
        for (int w = 0; w < 32; w++) ss += red[w];
        red[0] = 1.0f / ss;
    }
    __syncthreads();
    float inv = red[0];
    #pragma unroll
    for (int i = t; i < SS; i += 1024)
        attn_out[b * SS + i] = sv[i] * inv;
}

// ---------------------------------------------------------------------------
// k3: context partials from fp16 enc copy, 16B loads.
// grid(64, B), block(64). Thread t owns h = 8t..8t+7 (one uint4 per row).
// ---------------------------------------------------------------------------
__global__ void context_partial_kernel(const float* __restrict__ attn) {
    __shared__ float sa[64];
    int b  = blockIdx.y;
    int s0 = blockIdx.x * 64;
    int t  = threadIdx.x;           // 0..63
    sa[t] = attn[b * SS + s0 + t];
    __syncthreads();
    const __half* base = g_encH + ((size_t)b * SS + s0) * HH + t * 8;
    float a0 = 0.f, a1 = 0.f, a2 = 0.f, a3 = 0.f;
    float a4 = 0.f, a5 = 0.f, a6 = 0.f, a7 = 0.f;
    #pragma unroll 8
    for (int s = 0; s < 64; s++) {
        uint4 u = *(const uint4*)(base + (size_t)s * HH);
        float2 f0 = __half22float2(*(__half2*)&u.x);
        float2 f1 = __half22float2(*(__half2*)&u.y);
        float2 f2 = __half22float2(*(__half2*)&u.z);
        float2 f3 = __half22float2(*(__half2*)&u.w);
        float w = sa[s];
        a0 = fmaf(w, f0.x, a0); a1 = fmaf(w, f0.y, a1);
        a2 = fmaf(w, f1.x, a2); a3 = fmaf(w, f1.y, a3);
        a4 = fmaf(w, f2.x, a4); a5 = fmaf(w, f2.y, a5);
        a6 = fmaf(w, f3.x, a6); a7 = fmaf(w, f3.y, a7);
    }
    float* out = &g_ctx_part[((size_t)b * 64 + blockIdx.x) * HH + t * 8];
    *(float4*)out       = make_float4(a0, a1, a2, a3);
    *(float4*)(out + 4) = make_float4(a4, a5, a6, a7);
}

__global__ void context_reduce_kernel(float* __restrict__ ctx_out) {
    int b = blockIdx.x, h = threadIdx.x;
    float acc = 0.0f;
    #pragma unroll
    for (int sc = 0; sc < 64; sc++)
        acc += g_ctx_part[((size_t)b * 64 + sc) * HH + h];
    ctx_out[b * HH + h] = acc;
}

// ---------------------------------------------------------------------------
// entry point
// ---------------------------------------------------------------------------
extern "C" void kernel_launch(void* const* d_in, const int* in_sizes, int n_in,
                              void* d_out, int out_size) {
    const float* enc  = (const float*)d_in[0];
    const float* dh   = (const float*)d_in[1];
    const float* Wenc = (const float*)d_in[2];
    const float* benc = (const float*)d_in[3];
    const float* Wdec = (const float*)d_in[4];
    const float* bdec = (const float*)d_in[5];
    const float* We   = (const float*)d_in[6];

    float* ctx_out  = (float*)d_out;             // [B, H]
    float* attn_out = (float*)d_out + BB * HH;   // [B, S]

    cudaFuncSetAttribute(scores_mma_kernel,
                         cudaFuncAttributeMaxDynamicSharedMemorySize, SM_TOT);

    prep_fused_kernel<<<160, 256>>>(Wenc, dh, Wdec, bdec);
    scores_mma_kernel<<<(BB * SS) / TM, 512, SM_TOT>>>(enc, benc, We);
    softmax_kernel<<<BB, 1024>>>(attn_out);
    context_partial_kernel<<<dim3(64, BB), 64>>>(attn_out);
    context_reduce_kernel<<<BB, HH>>>(ctx_out);
}